// round 13
// baseline (speedup 1.0000x reference)
#include <cuda_runtime.h>
#include <cuda_fp16.h>
#include <cstdint>
#include <math.h>

// Problem constants
#define Ld  1024
#define Bd  4
#define Fd  512
#define Hd  8
#define Kd  64
#define Md  2048          // Lk + Lfuse
#define HBd (Hd*Bd)       // 32
#define HFd (Hd*Fd)       // 4096

// ---------------- scratch (device globals; no allocs allowed) ----------------
__device__ __half g_XHi[(size_t)5*4096*512], g_XLo[(size_t)5*4096*512]; // inputs split
__device__ __half g_WHi[512*512], g_WLo[512*512];                       // WK_w split
__device__ __half g_QrHi[HBd*Ld*Kd], g_QrLo[HBd*Ld*Kd];   // Q/K in split fp16
__device__ __half g_QtHi[HBd*Ld*Kd], g_QtLo[HBd*Ld*Kd];
__device__ __half g_KrHi[HBd*Md*Kd], g_KrLo[HBd*Md*Kd];
__device__ __half g_KtHi[HBd*Md*Kd], g_KtLo[HBd*Md*Kd];
__device__ float  g_Srgb[(size_t)HBd*Ld*Md];     // raw dots (fp32)
__device__ float  g_St  [(size_t)HBd*Ld*Md];
__device__ __half g_PrH[(size_t)HBd*Ld*Md];      // unnormalized softmax numerators (half)
__device__ __half g_PtH[(size_t)HBd*Ld*Md];
__device__ __half g_PxH[(size_t)HBd*Ld*Md];
__device__ __half g_VrT[(size_t)Bd*Fd*Md];       // V^T half: [b][f][m]
__device__ __half g_VtT[(size_t)Bd*Fd*Md];
__device__ float  g_pmax[(size_t)HBd*Ld*96];     // per-row partial maxes [3][32 mblks]
__device__ float  g_stats[HBd*Ld*6];

// ---------------- mma / ldmatrix / exp2 / cp.async helpers ----------------
__device__ __forceinline__ void mma_f16(float* c,
                                        uint32_t a0, uint32_t a1, uint32_t a2, uint32_t a3,
                                        uint32_t b0, uint32_t b1) {
    asm volatile(
        "mma.sync.aligned.m16n8k16.row.col.f32.f16.f16.f32 "
        "{%0,%1,%2,%3}, {%4,%5,%6,%7}, {%8,%9}, {%0,%1,%2,%3};"
        : "+f"(c[0]), "+f"(c[1]), "+f"(c[2]), "+f"(c[3])
        : "r"(a0), "r"(a1), "r"(a2), "r"(a3), "r"(b0), "r"(b1));
}
__device__ __forceinline__ void ldsm_x4(uint32_t* r, uint32_t addr) {
    asm volatile("ldmatrix.sync.aligned.m8n8.x4.shared.b16 {%0,%1,%2,%3}, [%4];"
                 : "=r"(r[0]), "=r"(r[1]), "=r"(r[2]), "=r"(r[3]) : "r"(addr));
}
__device__ __forceinline__ uint32_t h2exp2u(uint32_t x) {
    uint32_t r; asm("ex2.approx.f16x2 %0, %1;" : "=r"(r) : "r"(x)); return r;
}
__device__ __forceinline__ uint32_t pack_h2(float a, float b) {
    __half2 h = __floats2half2_rn(a, b);
    return *reinterpret_cast<uint32_t*>(&h);
}
__device__ __forceinline__ float2 h2f2(uint32_t u) {
    __half2 h = *reinterpret_cast<__half2*>(&u);
    return __half22float2(h);
}
__device__ __forceinline__ uint32_t smem_u32(const void* p) {
    uint32_t a;
    asm("{ .reg .u64 t; cvta.to.shared.u64 t, %1; cvt.u32.u64 %0, t; }" : "=r"(a) : "l"(p));
    return a;
}
#define CP_ASYNC16(dst, src) \
    asm volatile("cp.async.ca.shared.global [%0], [%1], 16;" :: "r"(dst), "l"(src) : "memory")
#define CP_COMMIT() asm volatile("cp.async.commit_group;" ::: "memory")
#define CP_WAIT1()  asm volatile("cp.async.wait_group 1;" ::: "memory")
#define CP_WAIT0()  asm volatile("cp.async.wait_group 0;" ::: "memory")

// =====================================================================
// Kernel A: split inputs + W into fp16 hi/lo pairs.
// grid: (1024, 6), block 256. y=0..4 -> X sources (4096x512), y=5 -> W.
// =====================================================================
__global__ __launch_bounds__(256)
void split_kernel(const float* __restrict__ q0, const float* __restrict__ q1,
                  const float* __restrict__ k0p, const float* __restrict__ k1p,
                  const float* __restrict__ kf,  const float* __restrict__ w)
{
    const int y = blockIdx.y;
    const float* srcs[6] = {q0, q1, k0p, k1p, kf, w};
    const float* src = srcs[y];
    const int N = (y == 5) ? (512*512) : (4096*512);
    const int el = (blockIdx.x * 256 + threadIdx.x) * 8;
    if (el >= N) return;
    __half* dHi = (y == 5) ? g_WHi : g_XHi + (size_t)y * 4096 * 512;
    __half* dLo = (y == 5) ? g_WLo : g_XLo + (size_t)y * 4096 * 512;

    float4 a = *reinterpret_cast<const float4*>(src + el);
    float4 b = *reinterpret_cast<const float4*>(src + el + 4);
    float v[8] = {a.x, a.y, a.z, a.w, b.x, b.y, b.z, b.w};
    __half hh[8], hl[8];
    #pragma unroll
    for (int i = 0; i < 8; i++) {
        hh[i] = __float2half_rn(v[i]);
        hl[i] = __float2half_rn(v[i] - __half2float(hh[i]));
    }
    *reinterpret_cast<uint4*>(dHi + el) = *reinterpret_cast<uint4*>(hh);
    *reinterpret_cast<uint4*>(dLo + el) = *reinterpret_cast<uint4*>(hl);
}

// =====================================================================
// Kernel 0: V transpose+convert -> half [b][f][m]
// =====================================================================
__global__ __launch_bounds__(256)
void vtrans_kernel(const float* __restrict__ rgbvalue,
                   const float* __restrict__ tvalue,
                   const float* __restrict__ fusevalue)
{
    __shared__ __half T[64][66];
    const int mBase = blockIdx.x * 64, fBase = blockIdx.y * 64;
    const int b = blockIdx.z & 3, sel = blockIdx.z >> 2;
    const float* v0 = sel ? tvalue : rgbvalue;
    __half* dst = sel ? g_VtT : g_VrT;
    const int tid = threadIdx.x;

    #pragma unroll
    for (int p = 0; p < 2; p++) {
        int id = tid + p * 256;
        int m  = id >> 3;
        int f8 = (id & 7) * 8;
        int mm = mBase + m;
        const float* src = (mm < Ld) ? v0 + ((size_t)mm * Bd + b) * Fd
                                     : fusevalue + ((size_t)(mm - Ld) * Bd + b) * Fd;
        float4 x = *reinterpret_cast<const float4*>(src + fBase + f8);
        float4 y = *reinterpret_cast<const float4*>(src + fBase + f8 + 4);
        T[m][f8+0] = __float2half(x.x); T[m][f8+1] = __float2half(x.y);
        T[m][f8+2] = __float2half(x.z); T[m][f8+3] = __float2half(x.w);
        T[m][f8+4] = __float2half(y.x); T[m][f8+5] = __float2half(y.y);
        T[m][f8+6] = __float2half(y.z); T[m][f8+7] = __float2half(y.w);
    }
    __syncthreads();
    #pragma unroll
    for (int p = 0; p < 2; p++) {
        int id = tid + p * 256;
        int f  = id >> 3;
        int m8 = (id & 7) * 8;
        __half tmp[8];
        #pragma unroll
        for (int k = 0; k < 8; k++) tmp[k] = T[m8 + k][f];
        *reinterpret_cast<uint4*>(dst + ((size_t)(b * Fd + fBase + f)) * Md + mBase + m8) =
            *reinterpret_cast<uint4*>(tmp);
    }
}

// =====================================================================
// Kernel 1: proj via split-fp16 mma + bias + L2 norm; hi/lo output.
// grid: (192, 8)
// =====================================================================
#define PST 72
#define PXT (128*PST)
#define PWT (64*PST)
#define PROJ_SMEM ((2*PXT + 2*PWT)*2)   // 55296 bytes

__global__ __launch_bounds__(256)
void proj_mma_kernel(const float* __restrict__ bias)
{
    extern __shared__ __half psm[];
    __half* XH = psm;
    __half* XL = XH + PXT;
    __half* WH = XL + PXT;
    __half* WL = WH + PWT;

    const int bx = blockIdx.x, h = blockIdx.y;
    const int tid = threadIdx.x;
    const int wid = tid >> 5, lane = tid & 31;
    const int r = lane >> 2, c = lane & 3;
    const int lr = lane & 7, g = lane >> 3;

    int dest, rb;
    if (bx < 32)       { dest = 0; rb = bx * 128; }
    else if (bx < 64)  { dest = 1; rb = (bx - 32) * 128; }
    else if (bx < 128) { dest = 2; rb = (bx - 64) * 128; }
    else               { dest = 3; rb = (bx - 128) * 128; }

    int srcIdx, srow;
    if (dest == 0)      { srcIdx = 0; srow = rb; }
    else if (dest == 1) { srcIdx = 1; srow = rb; }
    else if (dest == 2) { srcIdx = (rb < 4096) ? 2 : 4; srow = (rb < 4096) ? rb : rb - 4096; }
    else                { srcIdx = (rb < 4096) ? 3 : 4; srow = (rb < 4096) ? rb : rb - 4096; }

    const __half* xHi = g_XHi + (size_t)srcIdx * 4096 * 512 + (size_t)srow * 512;
    const __half* xLo = g_XLo + (size_t)srcIdx * 4096 * 512 + (size_t)srow * 512;
    const __half* wHi = g_WHi + (size_t)h * 64 * 512;
    const __half* wLo = g_WLo + (size_t)h * 64 * 512;

    __half *oHi, *oLo;
    int Lx;
    if (dest == 0)      { oHi = g_QrHi; oLo = g_QrLo; Lx = Ld; }
    else if (dest == 1) { oHi = g_QtHi; oLo = g_QtLo; Lx = Ld; }
    else if (dest == 2) { oHi = g_KrHi; oLo = g_KrLo; Lx = Md; }
    else                { oHi = g_KtHi; oLo = g_KtLo; Lx = Md; }

    const uint32_t uXH = smem_u32(XH), uXL = smem_u32(XL);
    const uint32_t uWH = smem_u32(WH), uWL = smem_u32(WL);
    const uint32_t aoff = (uint32_t)((wid*16 + lr + ((g & 1) << 3)) * PST + ((g >> 1) << 3)) * 2;
    const uint32_t boff = (uint32_t)((lr + ((g >> 1) << 3)) * PST + ((g & 1) << 3)) * 2;

    float acc[8][4] = {};

    for (int kc = 0; kc < 8; kc++) {
        const int k0 = kc * 64;
        #pragma unroll
        for (int p = 0; p < 4; p++) {
            int id = tid + p * 256;
            int row = id >> 3, seg = id & 7;
            uint32_t d = (uint32_t)(row * PST + seg * 8) * 2;
            CP_ASYNC16(uXH + d, xHi + (size_t)row * 512 + k0 + seg * 8);
            CP_ASYNC16(uXL + d, xLo + (size_t)row * 512 + k0 + seg * 8);
        }
        #pragma unroll
        for (int p = 0; p < 2; p++) {
            int id = tid + p * 256;
            int row = id >> 3, seg = id & 7;
            uint32_t d = (uint32_t)(row * PST + seg * 8) * 2;
            CP_ASYNC16(uWH + d, wHi + (size_t)row * 512 + k0 + seg * 8);
            CP_ASYNC16(uWL + d, wLo + (size_t)row * 512 + k0 + seg * 8);
        }
        CP_COMMIT();
        CP_WAIT0();
        __syncthreads();

        #pragma unroll
        for (int ks = 0; ks < 4; ks++) {
            const uint32_t ko = ks * 32;
            uint32_t ah[4], al[4];
            ldsm_x4(ah, uXH + aoff + ko);
            ldsm_x4(al, uXL + aoff + ko);
            #pragma unroll
            for (int np = 0; np < 4; np++) {
                const uint32_t no = (uint32_t)(np * 16 * PST) * 2;
                uint32_t bh[4], bl[4];
                ldsm_x4(bh, uWH + boff + no + ko);
                ldsm_x4(bl, uWL + boff + no + ko);
                #pragma unroll
                for (int hn = 0; hn < 2; hn++) {
                    int nt = np * 2 + hn;
                    uint32_t b0 = hn * 2, b1 = hn * 2 + 1;
                    mma_f16(acc[nt], ah[0], ah[1], ah[2], ah[3], bh[b0], bh[b1]);
                    mma_f16(acc[nt], ah[0], ah[1], ah[2], ah[3], bl[b0], bl[b1]);
                    mma_f16(acc[nt], al[0], al[1], al[2], al[3], bh[b0], bh[b1]);
                }
            }
        }
        __syncthreads();
    }

    #pragma unroll
    for (int nt = 0; nt < 8; nt++) {
        int col = nt * 8 + 2 * c;
        float b0 = bias[h*64 + col], b1 = bias[h*64 + col + 1];
        acc[nt][0] += b0; acc[nt][2] += b0;
        acc[nt][1] += b1; acc[nt][3] += b1;
    }

    float s0 = 0.f, s1 = 0.f;
    #pragma unroll
    for (int nt = 0; nt < 8; nt++) {
        s0 += acc[nt][0]*acc[nt][0] + acc[nt][1]*acc[nt][1];
        s1 += acc[nt][2]*acc[nt][2] + acc[nt][3]*acc[nt][3];
    }
    s0 += __shfl_xor_sync(0xffffffffu, s0, 1);
    s0 += __shfl_xor_sync(0xffffffffu, s0, 2);
    s1 += __shfl_xor_sync(0xffffffffu, s1, 1);
    s1 += __shfl_xor_sync(0xffffffffu, s1, 2);
    const float inv0 = 1.0f / fmaxf(sqrtf(s0), 1e-12f);
    const float inv1 = 1.0f / fmaxf(sqrtf(s1), 1e-12f);

    const int gr0 = rb + wid * 16 + r;
    const int gr1 = gr0 + 8;
    const int l0 = gr0 >> 2, bb0 = gr0 & 3;
    const int l1 = gr1 >> 2, bb1 = gr1 & 3;
    const size_t off0 = ((size_t)(h*4 + bb0) * Lx + l0) * 64;
    const size_t off1 = ((size_t)(h*4 + bb1) * Lx + l1) * 64;

    #pragma unroll
    for (int nt = 0; nt < 8; nt++) {
        int col = nt * 8 + 2 * c;
        float v0 = acc[nt][0] * inv0, v1 = acc[nt][1] * inv0;
        __half h0 = __float2half_rn(v0), h1 = __float2half_rn(v1);
        __half e0 = __float2half_rn(v0 - __half2float(h0));
        __half e1 = __float2half_rn(v1 - __half2float(h1));
        *reinterpret_cast<__half2*>(oHi + off0 + col) = __halves2half2(h0, h1);
        *reinterpret_cast<__half2*>(oLo + off0 + col) = __halves2half2(e0, e1);
        float w0 = acc[nt][2] * inv1, w1 = acc[nt][3] * inv1;
        __half j0 = __float2half_rn(w0), j1 = __float2half_rn(w1);
        __half f0 = __float2half_rn(w0 - __half2float(j0));
        __half f1 = __float2half_rn(w1 - __half2float(j1));
        *reinterpret_cast<__half2*>(oHi + off1 + col) = __halves2half2(j0, j1);
        *reinterpret_cast<__half2*>(oLo + off1 + col) = __halves2half2(f0, f1);
    }
}

// =====================================================================
// Kernel 2: dot via split-fp16 mma. NEW: S writes staged through smem
// and emitted as coalesced 128B float4 runs (cuts STG wavefronts ~4x).
// grid: (Md/64, Ld/128, HBd), block 256, dynamic smem 110592 B
// =====================================================================
#define DST 72
#define DQT (128*DST)
#define DKT (64*DST)
#define DOT_SMEM ((4*DQT + 4*DKT)*2)

__global__ __launch_bounds__(256, 2)
void dot_kernel()
{
    extern __shared__ __half dsm[];
    __half* QrH = dsm;
    __half* QrL = QrH + DQT;
    __half* QtH = QrL + DQT;
    __half* QtL = QtH + DQT;
    __half* KrH = QtL + DQT;
    __half* KrL = KrH + DKT;
    __half* KtH = KrL + DKT;
    __half* KtL = KtH + DKT;

    const int hb = blockIdx.z;
    const int mBase = blockIdx.x * 64, lBase = blockIdx.y * 128;
    const int mblk = blockIdx.x;
    const int tid = threadIdx.x;
    const int wid = tid >> 5, lane = tid & 31;
    const int r = lane >> 2, c = lane & 3;
    const int lr = lane & 7, g = lane >> 3;

    const __half* gq[4] = { g_QrHi + ((size_t)hb*Ld + lBase)*Kd, g_QrLo + ((size_t)hb*Ld + lBase)*Kd,
                            g_QtHi + ((size_t)hb*Ld + lBase)*Kd, g_QtLo + ((size_t)hb*Ld + lBase)*Kd };
    const __half* gk[4] = { g_KrHi + ((size_t)hb*Md + mBase)*Kd, g_KrLo + ((size_t)hb*Md + mBase)*Kd,
                            g_KtHi + ((size_t)hb*Md + mBase)*Kd, g_KtLo + ((size_t)hb*Md + mBase)*Kd };
    __half* sq[4] = { QrH, QrL, QtH, QtL };
    __half* sk[4] = { KrH, KrL, KtH, KtL };

    #pragma unroll
    for (int s = 0; s < 4; s++) {
        uint32_t qb = smem_u32(sq[s]);
        #pragma unroll
        for (int p = 0; p < 4; p++) {
            int id = tid + p * 256;
            int row = id >> 3, ch = id & 7;
            CP_ASYNC16(qb + (uint32_t)(row * DST + ch * 8) * 2, gq[s] + (size_t)row * Kd + ch * 8);
        }
        uint32_t kb = smem_u32(sk[s]);
        #pragma unroll
        for (int p = 0; p < 2; p++) {
            int id = tid + p * 256;
            int row = id >> 3, ch = id & 7;
            CP_ASYNC16(kb + (uint32_t)(row * DST + ch * 8) * 2, gk[s] + (size_t)row * Kd + ch * 8);
        }
    }
    CP_COMMIT();
    CP_WAIT0();
    __syncthreads();

    float accR[8][4] = {}, accT[8][4] = {};

    const int la = wid * 16;
    const uint32_t aoff = (uint32_t)((la + lr + ((g & 1) << 3)) * DST + ((g >> 1) << 3)) * 2;
    const uint32_t boff = (uint32_t)((lr + ((g >> 1) << 3)) * DST + ((g & 1) << 3)) * 2;
    const uint32_t uQrH = smem_u32(QrH), uQrL = smem_u32(QrL);
    const uint32_t uQtH = smem_u32(QtH), uQtL = smem_u32(QtL);
    const uint32_t uKrH = smem_u32(KrH), uKrL = smem_u32(KrL);
    const uint32_t uKtH = smem_u32(KtH), uKtL = smem_u32(KtL);

    #pragma unroll
    for (int ks = 0; ks < 4; ks++) {
        const uint32_t ko = ks * 32;
        uint32_t qrh[4], qrl[4], qth[4], qtl[4];
        ldsm_x4(qrh, uQrH + aoff + ko);
        ldsm_x4(qrl, uQrL + aoff + ko);
        ldsm_x4(qth, uQtH + aoff + ko);
        ldsm_x4(qtl, uQtL + aoff + ko);
        #pragma unroll
        for (int np = 0; np < 4; np++) {
            const uint32_t no = (uint32_t)(np * 16 * DST) * 2;
            uint32_t krh[4], krl[4], kth[4], ktl[4];
            ldsm_x4(krh, uKrH + boff + no + ko);
            ldsm_x4(krl, uKrL + boff + no + ko);
            ldsm_x4(kth, uKtH + boff + no + ko);
            ldsm_x4(ktl, uKtL + boff + no + ko);
            #pragma unroll
            for (int half_nt = 0; half_nt < 2; half_nt++) {
                int nt = np * 2 + half_nt;
                uint32_t b0 = half_nt * 2, b1 = half_nt * 2 + 1;
                mma_f16(accR[nt], qrh[0], qrh[1], qrh[2], qrh[3], krh[b0], krh[b1]);
                mma_f16(accR[nt], qrh[0], qrh[1], qrh[2], qrh[3], krl[b0], krl[b1]);
                mma_f16(accR[nt], qrl[0], qrl[1], qrl[2], qrl[3], krh[b0], krh[b1]);
                mma_f16(accT[nt], qth[0], qth[1], qth[2], qth[3], kth[b0], kth[b1]);
                mma_f16(accT[nt], qth[0], qth[1], qth[2], qth[3], ktl[b0], ktl[b1]);
                mma_f16(accT[nt], qtl[0], qtl[1], qtl[2], qtl[3], kth[b0], kth[b1]);
            }
        }
    }

    // ---- partial maxes (from registers, before smem reuse) ----
    const int l0 = lBase + la + r;
    const int l1 = l0 + 8;
    float p1a = -1e30f, p1b = -1e30f, p2a = -1e30f, p2b = -1e30f, p3a = -1e30f, p3b = -1e30f;
    #pragma unroll
    for (int nt = 0; nt < 8; nt++) {
        p1a = fmaxf(p1a, fmaxf(accR[nt][0], accR[nt][1]));
        p1b = fmaxf(p1b, fmaxf(accR[nt][2], accR[nt][3]));
        p2a = fmaxf(p2a, fmaxf(accT[nt][0], accT[nt][1]));
        p2b = fmaxf(p2b, fmaxf(accT[nt][2], accT[nt][3]));
        p3a = fmaxf(p3a, fmaxf(accR[nt][0]*accT[nt][0], accR[nt][1]*accT[nt][1]));
        p3b = fmaxf(p3b, fmaxf(accR[nt][2]*accT[nt][2], accR[nt][3]*accT[nt][3]));
    }
    #pragma unroll
    for (int o = 1; o <= 2; o <<= 1) {
        p1a = fmaxf(p1a, __shfl_xor_sync(0xffffffffu, p1a, o));
        p1b = fmaxf(p1b, __shfl_xor_sync(0xffffffffu, p1b, o));
        p2a = fmaxf(p2a, __shfl_xor_sync(0xffffffffu, p2a, o));
        p2b = fmaxf(p2b, __shfl_xor_sync(0xffffffffu, p2b, o));
        p3a = fmaxf(p3a, __shfl_xor_sync(0xffffffffu, p3a, o));
        p3b = fmaxf(p3b, __shfl_xor_sync(0xffffffffu, p3b, o));
    }
    if (c == 0) {
        size_t ra = (size_t)hb * Ld + l0;
        size_t rb = (size_t)hb * Ld + l1;
        g_pmax[ra*96 +      mblk] = p1a;  g_pmax[rb*96 +      mblk] = p1b;
        g_pmax[ra*96 + 32 + mblk] = p2a;  g_pmax[rb*96 + 32 + mblk] = p2b;
        g_pmax[ra*96 + 64 + mblk] = p3a;  g_pmax[rb*96 + 64 + mblk] = p3b;
    }

    // ---- staged coalesced S writes (reuse operand smem as 128x68 fp32) ----
    __syncthreads();   // all ldsm reads of dsm complete before overwrite
    float (*Stile)[68] = reinterpret_cast<float(*)[68]>(dsm);
    const int orow = tid >> 1, oseg = tid & 1;   // 128 rows x 2 segs of 32 floats

    // stream R
    #pragma unroll
    for (int nt = 0; nt < 8; nt++) {
        int col = nt * 8 + 2 * c;
        *reinterpret_cast<float2*>(&Stile[la + r    ][col]) = make_float2(accR[nt][0], accR[nt][1]);
        *reinterpret_cast<float2*>(&Stile[la + r + 8][col]) = make_float2(accR[nt][2], accR[nt][3]);
    }
    __syncthreads();
    {
        float* dst = g_Srgb + ((size_t)hb * Ld + lBase + orow) * Md + mBase + oseg * 32;
        const float* src = &Stile[orow][oseg * 32];
        #pragma unroll
        for (int i = 0; i < 8; i++)
            *reinterpret_cast<float4*>(dst + i * 4) = *reinterpret_cast<const float4*>(src + i * 4);
    }
    __syncthreads();

    // stream T
    #pragma unroll
    for (int nt = 0; nt < 8; nt++) {
        int col = nt * 8 + 2 * c;
        *reinterpret_cast<float2*>(&Stile[la + r    ][col]) = make_float2(accT[nt][0], accT[nt][1]);
        *reinterpret_cast<float2*>(&Stile[la + r + 8][col]) = make_float2(accT[nt][2], accT[nt][3]);
    }
    __syncthreads();
    {
        float* dst = g_St + ((size_t)hb * Ld + lBase + orow) * Md + mBase + oseg * 32;
        const float* src = &Stile[orow][oseg * 32];
        #pragma unroll
        for (int i = 0; i < 8; i++)
            *reinterpret_cast<float4*>(dst + i * 4) = *reinterpret_cast<const float4*>(src + i * 4);
    }
}

// =====================================================================
// Kernel 3: stats (unchanged)
// =====================================================================
__global__ __launch_bounds__(256)
void stats_kernel()
{
    const int row = blockIdx.x;
    const float* sr = g_Srgb + (size_t)row * Md;
    const float* st = g_St   + (size_t)row * Md;
    __half* pr = g_PrH + (size_t)row * Md;
    __half* pt = g_PtH + (size_t)row * Md;
    __half* px = g_PxH + (size_t)row * Md;
    const int tid = threadIdx.x;
    const int lane = tid & 31, wid = tid >> 5;
    __shared__ float smax[3];
    __shared__ float sm[8][3];

    if (wid < 3) {
        float v = g_pmax[(size_t)row * 96 + wid*32 + lane];
        #pragma unroll
        for (int o = 16; o > 0; o >>= 1)
            v = fmaxf(v, __shfl_xor_sync(0xffffffffu, v, o));
        if (lane == 0) smax[wid] = v;
    }
    __syncthreads();

    const float L2E = 1.44269504088896340736f;
    const float m1 = 100.f * smax[0], m2 = 100.f * smax[1], m3 = smax[2];
    const float c100 = 100.f * L2E;
    const float mm1 = m1 * L2E, mm2 = m2 * L2E, mm3 = m3 * L2E;

    float s1 = 0.f, s2 = 0.f, s3 = 0.f;
    #pragma unroll
    for (int it = 0; it < 2; it++) {
        int i = (tid + it * 256) * 4;
        float4 a = *reinterpret_cast<const float4*>(sr + i);
        float4 b = *reinterpret_cast<const float4*>(st + i);

        uint32_t u0 = h2exp2u(pack_h2(fmaf(c100, a.x, -mm1), fmaf(c100, a.y, -mm1)));
        uint32_t u1 = h2exp2u(pack_h2(fmaf(c100, a.z, -mm1), fmaf(c100, a.w, -mm1)));
        *reinterpret_cast<uint2*>(pr + i) = make_uint2(u0, u1);
        float2 f0 = h2f2(u0), f1 = h2f2(u1);
        s1 += (f0.x + f0.y) + (f1.x + f1.y);

        u0 = h2exp2u(pack_h2(fmaf(c100, b.x, -mm2), fmaf(c100, b.y, -mm2)));
        u1 = h2exp2u(pack_h2(fmaf(c100, b.z, -mm2), fmaf(c100, b.w, -mm2)));
        *reinterpret_cast<uint2*>(pt + i) = make_uint2(u0, u1);
        f0 = h2f2(u0); f1 = h2f2(u1);
        s2 += (f0.x + f0.y) + (f1.x + f1.y);

        u0 = h2exp2u(pack_h2(fmaf(L2E, a.x*b.x, -mm3), fmaf(L2E, a.y*b.y, -mm3)));
        u1 = h2exp2u(pack_h2(fmaf(L2E, a.z*b.z, -mm3), fmaf(L2E, a.w*b.w, -mm3)));
        *reinterpret_cast<uint2*>(px + i) = make_uint2(u0, u1);
        f0 = h2f2(u0); f1 = h2f2(u1);
        s3 += (f0.x + f0.y) + (f1.x + f1.y);
    }
    #pragma unroll
    for (int o = 16; o > 0; o >>= 1) {
        s1 += __shfl_xor_sync(0xffffffffu, s1, o);
        s2 += __shfl_xor_sync(0xffffffffu, s2, o);
        s3 += __shfl_xor_sync(0xffffffffu, s3, o);
    }
    if (lane == 0) { sm[wid][0] = s1; sm[wid][1] = s2; sm[wid][2] = s3; }
    __syncthreads();
    if (tid == 0) {
        s1 = s2 = s3 = 0.f;
        #pragma unroll
        for (int w = 0; w < 8; w++) { s1 += sm[w][0]; s2 += sm[w][1]; s3 += sm[w][2]; }
        float* o = g_stats + (size_t)row * 6;
        o[0] = m1; o[1] = s1; o[2] = m2; o[3] = s2; o[4] = m3; o[5] = s3;
    }
}

// =====================================================================
// Kernel 4: attend — fp16 mma, tile 64l x 128f, 2-stage cp.async double
// buffer. 8 warps = 2(l) x 4(f), each 32x32. (unchanged from R11)
// grid: (F/128, L/64, HB), block 256, dynamic smem 71680 B
// =====================================================================
#define AST    40
#define PTILE  (64*AST)             // 2560 halves per P tile
#define VTILE  (128*AST)            // 5120 halves per V tile
#define ASTG   (3*PTILE + 2*VTILE)  // 17920 halves per stage
#define ATT_SMEM (2*ASTG*2)         // 71680 bytes
#define NCHUNK (Md/32)              // 64

__global__ __launch_bounds__(256, 1)
void attend_mma_kernel(float* __restrict__ out)
{
    extern __shared__ __half ash[];
    const int hb = blockIdx.z;
    const int h  = hb / Bd, b = hb % Bd;
    const int fBase = blockIdx.x * 128, lBase = blockIdx.y * 64;
    const int tid = threadIdx.x;
    const int wid = tid >> 5, lane = tid & 31;
    const int wl = wid & 1, wf = wid >> 1;     // 2 l-groups x 4 f-groups
    const int r = lane >> 2, c = lane & 3;
    const int lr = lane & 7, g = lane >> 3;

    const __half* s0 = g_PrH + ((size_t)hb * Ld + lBase) * Md;
    const __half* s1 = g_PtH + ((size_t)hb * Ld + lBase) * Md;
    const __half* s2 = g_PxH + ((size_t)hb * Ld + lBase) * Md;
    const __half* s3 = g_VrT + ((size_t)(b * Fd + fBase)) * Md;
    const __half* s4 = g_VtT + ((size_t)(b * Fd + fBase)) * Md;

    const uint32_t sbase = smem_u32(ash);
    const int prow = tid >> 2, pseg = tid & 3;               // 64 rows x 4 16B-segs
    const uint32_t dP  = (uint32_t)(prow * AST + pseg * 8) * 2;
    const uint32_t dV0 = dP;                                  // V row prow
    const uint32_t dV1 = (uint32_t)((prow + 64) * AST + pseg * 8) * 2;
    const size_t gP  = (size_t)prow * Md + pseg * 8;
    const size_t gV1 = (size_t)(prow + 64) * Md + pseg * 8;

    // ldmatrix fragment offsets within a stage (bytes)
    uint32_t aoff[2];
    #pragma unroll
    for (int af = 0; af < 2; af++)
        aoff[af] = (uint32_t)((wl*32 + af*16 + lr + ((g & 1) << 3)) * AST + ((g >> 1) << 3)) * 2;
    const uint32_t boff = (uint32_t)((wf*32 + lr + ((g >> 1) << 3)) * AST + ((g & 1) << 3)) * 2;

    float acc[4][2][4][4] = {};   // [out][afrag][ntile][reg]

    // prologue: stage 0 <- chunk 0
    {
        uint32_t st = sbase;
        CP_ASYNC16(st + 0*PTILE*2 + dP, s0 + gP);
        CP_ASYNC16(st + 1*PTILE*2 + dP, s1 + gP);
        CP_ASYNC16(st + 2*PTILE*2 + dP, s2 + gP);
        CP_ASYNC16(st + 3*PTILE*2 + dV0, s3 + gP);
        CP_ASYNC16(st + 3*PTILE*2 + dV1, s3 + gV1);
        CP_ASYNC16(st + (3*PTILE + VTILE)*2 + dV0, s4 + gP);
        CP_ASYNC16(st + (3*PTILE + VTILE)*2 + dV1, s4 + gV1);
    }
    CP_COMMIT();

    for (int cc = 0; cc < NCHUNK; cc++) {
        if (cc + 1 < NCHUNK) {
            size_t o1 = (size_t)(cc + 1) * 32;
            uint32_t st = sbase + (uint32_t)(((cc + 1) & 1) * ASTG) * 2;
            CP_ASYNC16(st + 0*PTILE*2 + dP, s0 + gP + o1);
            CP_ASYNC16(st + 1*PTILE*2 + dP, s1 + gP + o1);
            CP_ASYNC16(st + 2*PTILE*2 + dP, s2 + gP + o1);
            CP_ASYNC16(st + 3*PTILE*2 + dV0, s3 + gP + o1);
            CP_ASYNC16(st + 3*PTILE*2 + dV1, s3 + gV1 + o1);
            CP_ASYNC16(st + (3*PTILE + VTILE)*2 + dV0, s4 + gP + o1);
            CP_ASYNC16(st + (3*PTILE + VTILE)*2 + dV1, s4 + gV1 + o1);
        }
        CP_COMMIT();
        CP_WAIT1();
        __syncthreads();

        const uint32_t stg = sbase + (uint32_t)((cc & 1) * ASTG) * 2;
        const uint32_t uPr = stg;
        const uint32_t uPt = stg + 1*PTILE*2;
        const uint32_t uPx = stg + 2*PTILE*2;
        const uint32_t uVr = stg + 3*PTILE*2;
        const uint32_t uVt = stg + (3*PTILE + VTILE)*2;

        #pragma unroll
        for (int ks = 0; ks < 2; ks++) {
            const uint32_t ko = ks * 32;
            uint32_t ar[2][4], at[2][4], ax[2][4];
            #pragma unroll
            for (int af = 0; af < 2; af++) {
                ldsm_x4(ar[af], uPr + aoff[af] + ko);
                ldsm_x4(at[af], uPt + aoff[af] + ko);
                ldsm_x4(ax[af], uPx + aoff[af] + ko);
            }
            #pragma unroll
            for (int np = 0; np < 2; np++) {
                const uint32_t no = (uint32_t)(np * 16 * AST) * 2;
                uint32_t vr[4], vt[4];
                ldsm_x4(vr, uVr + boff + no + ko);
                ldsm_x4(vt, uVt + boff + no + ko);
                #pragma unroll
                for (int af = 0; af < 2; af++) {
                    #pragma unroll
                    for (int hn = 0; hn < 2; hn++) {
                        int nt = np * 2 + hn;
                        uint32_t b0 = hn * 2, b1 = hn * 2 + 1;
                        mma_f16(acc[0][af][nt], ar[af][0], ar[af][1], ar[af][2], ar[af][3], vr[b0], vr[b1]);
                        mma_f16(acc[1][af][nt], at[af][0], at[af][1], at[af][2], at[af][3], vt[b0], vt[b1]);
                        mma_f16(acc[2][af][nt], ax[af][0], ax[af][1], ax[af][2], ax[af][3], vt[b0], vt[b1]);
                        mma_f16(acc[3][af][nt], ax[af][0], ax[af][1], ax[af][2], ax[af][3], vr[b0], vr[b1]);
                    }
                }
            }
        }
        __syncthreads();
    }

    const size_t OSZ = (size_t)Ld * Bd * HFd;
    #pragma unroll
    for (int af = 0; af < 2; af++) {
        const int l0 = lBase + wl * 32 + af * 16 + r;
        const int l1 = l0 + 8;
        const float* st0 = g_stats + ((size_t)hb * Ld + l0) * 6;
        const float* st1 = g_stats + ((size_t)hb * Ld + l1) * 6;
        const float inv0[4] = {1.f/st0[1], 1.f/st0[3], 1.f/st0[5], 1.f/st0[5]};
        const float inv1[4] = {1.f/st1[1], 1.f/st1[3], 1.f/st1[5], 1.f/st1[5]};
        const size_t base0 = ((size_t)l0 * Bd + b) * HFd + (size_t)h * Fd;
        const size_t base1 = ((size_t)l1 * Bd + b) * HFd + (size_t)h * Fd;
        #pragma unroll
        for (int d = 0; d < 4; d++) {
            #pragma unroll
            for (int nt = 0; nt < 4; nt++) {
                int f = fBase + wf * 32 + nt * 8 + 2 * c;
                *reinterpret_cast<float2*>(out + d*OSZ + base0 + f) =
                    make_float2(acc[d][af][nt][0] * inv0[d], acc[d][af][nt][1] * inv0[d]);
                *reinterpret_cast<float2*>(out + d*OSZ + base1 + f) =
                    make_float2(acc[d][af][nt][2] * inv1[d], acc[d][af][nt][3] * inv1[d]);
            }
        }
    }
}

// =====================================================================
extern "C" void kernel_launch(void* const* d_in, const int* in_sizes, int n_in,
                              void* d_out, int out_size)
{
    const float* rgbquery  = (const float*)d_in[0];
    const float* rgbkey    = (const float*)d_in[1];
    const float* rgbvalue  = (const float*)d_in[2];
    const float* tquery    = (const float*)d_in[3];
    const float* tkey      = (const float*)d_in[4];
    const float* tvalue    = (const float*)d_in[5];
    const float* fusekey   = (const float*)d_in[6];
    const float* fusevalue = (const float*)d_in[7];
    const float* WK_w      = (const float*)d_in[8];
    const float* WK_b      = (const float*)d_in[9];
    float* out = (float*)d_out;

    cudaFuncSetAttribute(proj_mma_kernel, cudaFuncAttributeMaxDynamicSharedMemorySize, PROJ_SMEM);
    cudaFuncSetAttribute(dot_kernel, cudaFuncAttributeMaxDynamicSharedMemorySize, DOT_SMEM);
    cudaFuncSetAttribute(attend_mma_kernel, cudaFuncAttributeMaxDynamicSharedMemorySize, ATT_SMEM);

    split_kernel<<<dim3(1024, 6), 256>>>(rgbquery, tquery, rgbkey, tkey, fusekey, WK_w);
    vtrans_kernel<<<dim3(Md/64, Fd/64, Bd*2), 256>>>(rgbvalue, tvalue, fusevalue);
    proj_mma_kernel<<<dim3(192, Hd), 256, PROJ_SMEM>>>(WK_b);
    dot_kernel<<<dim3(Md/64, Ld/128, HBd), 256, DOT_SMEM>>>();
    stats_kernel<<<HBd*Ld, 256>>>();
    attend_mma_kernel<<<dim3(Fd/128, Ld/64, HBd), 256, ATT_SMEM>>>(out);
}

// round 14
// speedup vs baseline: 1.1012x; 1.1012x over previous
#include <cuda_runtime.h>
#include <cuda_fp16.h>
#include <cstdint>
#include <math.h>

// Problem constants
#define Ld  1024
#define Bd  4
#define Fd  512
#define Hd  8
#define Kd  64
#define Md  2048          // Lk + Lfuse
#define HBd (Hd*Bd)       // 32
#define HFd (Hd*Fd)       // 4096

// ---------------- scratch (device globals; no allocs allowed) ----------------
__device__ __half g_XHi[(size_t)5*4096*512], g_XLo[(size_t)5*4096*512]; // inputs split
__device__ __half g_WHi[512*512], g_WLo[512*512];                       // WK_w split
__device__ __half g_QrHi[HBd*Ld*Kd], g_QrLo[HBd*Ld*Kd];   // Q/K in split fp16
__device__ __half g_QtHi[HBd*Ld*Kd], g_QtLo[HBd*Ld*Kd];
__device__ __half g_KrHi[HBd*Md*Kd], g_KrLo[HBd*Md*Kd];
__device__ __half g_KtHi[HBd*Md*Kd], g_KtLo[HBd*Md*Kd];
__device__ float  g_Srgb[(size_t)HBd*Ld*Md];     // raw dots (fp32)
__device__ float  g_St  [(size_t)HBd*Ld*Md];
__device__ __half g_PrH[(size_t)HBd*Ld*Md];      // unnormalized softmax numerators (half)
__device__ __half g_PtH[(size_t)HBd*Ld*Md];
__device__ __half g_PxH[(size_t)HBd*Ld*Md];
__device__ __half g_VrT[(size_t)Bd*Fd*Md];       // V^T half: [b][f][m]
__device__ __half g_VtT[(size_t)Bd*Fd*Md];
__device__ float  g_pmax[(size_t)HBd*Ld*192];    // per-row partial maxes [3][64 slots]
__device__ float  g_stats[HBd*Ld*6];

// ---------------- mma / ldmatrix / exp2 / cp.async helpers ----------------
__device__ __forceinline__ void mma_f16(float* c,
                                        uint32_t a0, uint32_t a1, uint32_t a2, uint32_t a3,
                                        uint32_t b0, uint32_t b1) {
    asm volatile(
        "mma.sync.aligned.m16n8k16.row.col.f32.f16.f16.f32 "
        "{%0,%1,%2,%3}, {%4,%5,%6,%7}, {%8,%9}, {%0,%1,%2,%3};"
        : "+f"(c[0]), "+f"(c[1]), "+f"(c[2]), "+f"(c[3])
        : "r"(a0), "r"(a1), "r"(a2), "r"(a3), "r"(b0), "r"(b1));
}
__device__ __forceinline__ void ldsm_x4(uint32_t* r, uint32_t addr) {
    asm volatile("ldmatrix.sync.aligned.m8n8.x4.shared.b16 {%0,%1,%2,%3}, [%4];"
                 : "=r"(r[0]), "=r"(r[1]), "=r"(r[2]), "=r"(r[3]) : "r"(addr));
}
__device__ __forceinline__ uint32_t h2exp2u(uint32_t x) {
    uint32_t r; asm("ex2.approx.f16x2 %0, %1;" : "=r"(r) : "r"(x)); return r;
}
__device__ __forceinline__ uint32_t pack_h2(float a, float b) {
    __half2 h = __floats2half2_rn(a, b);
    return *reinterpret_cast<uint32_t*>(&h);
}
__device__ __forceinline__ float2 h2f2(uint32_t u) {
    __half2 h = *reinterpret_cast<__half2*>(&u);
    return __half22float2(h);
}
__device__ __forceinline__ uint32_t smem_u32(const void* p) {
    uint32_t a;
    asm("{ .reg .u64 t; cvta.to.shared.u64 t, %1; cvt.u32.u64 %0, t; }" : "=r"(a) : "l"(p));
    return a;
}
#define CP_ASYNC16(dst, src) \
    asm volatile("cp.async.ca.shared.global [%0], [%1], 16;" :: "r"(dst), "l"(src) : "memory")
#define CP_COMMIT() asm volatile("cp.async.commit_group;" ::: "memory")
#define CP_WAIT1()  asm volatile("cp.async.wait_group 1;" ::: "memory")
#define CP_WAIT0()  asm volatile("cp.async.wait_group 0;" ::: "memory")

// =====================================================================
// Kernel A: split inputs + W into fp16 hi/lo pairs.
// grid: (1024, 6), block 256. y=0..4 -> X sources (4096x512), y=5 -> W.
// =====================================================================
__global__ __launch_bounds__(256)
void split_kernel(const float* __restrict__ q0, const float* __restrict__ q1,
                  const float* __restrict__ k0p, const float* __restrict__ k1p,
                  const float* __restrict__ kf,  const float* __restrict__ w)
{
    const int y = blockIdx.y;
    const float* srcs[6] = {q0, q1, k0p, k1p, kf, w};
    const float* src = srcs[y];
    const int N = (y == 5) ? (512*512) : (4096*512);
    const int el = (blockIdx.x * 256 + threadIdx.x) * 8;
    if (el >= N) return;
    __half* dHi = (y == 5) ? g_WHi : g_XHi + (size_t)y * 4096 * 512;
    __half* dLo = (y == 5) ? g_WLo : g_XLo + (size_t)y * 4096 * 512;

    float4 a = *reinterpret_cast<const float4*>(src + el);
    float4 b = *reinterpret_cast<const float4*>(src + el + 4);
    float v[8] = {a.x, a.y, a.z, a.w, b.x, b.y, b.z, b.w};
    __half hh[8], hl[8];
    #pragma unroll
    for (int i = 0; i < 8; i++) {
        hh[i] = __float2half_rn(v[i]);
        hl[i] = __float2half_rn(v[i] - __half2float(hh[i]));
    }
    *reinterpret_cast<uint4*>(dHi + el) = *reinterpret_cast<uint4*>(hh);
    *reinterpret_cast<uint4*>(dLo + el) = *reinterpret_cast<uint4*>(hl);
}

// =====================================================================
// Kernel 0: V transpose+convert -> half [b][f][m]
// =====================================================================
__global__ __launch_bounds__(256)
void vtrans_kernel(const float* __restrict__ rgbvalue,
                   const float* __restrict__ tvalue,
                   const float* __restrict__ fusevalue)
{
    __shared__ __half T[64][66];
    const int mBase = blockIdx.x * 64, fBase = blockIdx.y * 64;
    const int b = blockIdx.z & 3, sel = blockIdx.z >> 2;
    const float* v0 = sel ? tvalue : rgbvalue;
    __half* dst = sel ? g_VtT : g_VrT;
    const int tid = threadIdx.x;

    #pragma unroll
    for (int p = 0; p < 2; p++) {
        int id = tid + p * 256;
        int m  = id >> 3;
        int f8 = (id & 7) * 8;
        int mm = mBase + m;
        const float* src = (mm < Ld) ? v0 + ((size_t)mm * Bd + b) * Fd
                                     : fusevalue + ((size_t)(mm - Ld) * Bd + b) * Fd;
        float4 x = *reinterpret_cast<const float4*>(src + fBase + f8);
        float4 y = *reinterpret_cast<const float4*>(src + fBase + f8 + 4);
        T[m][f8+0] = __float2half(x.x); T[m][f8+1] = __float2half(x.y);
        T[m][f8+2] = __float2half(x.z); T[m][f8+3] = __float2half(x.w);
        T[m][f8+4] = __float2half(y.x); T[m][f8+5] = __float2half(y.y);
        T[m][f8+6] = __float2half(y.z); T[m][f8+7] = __float2half(y.w);
    }
    __syncthreads();
    #pragma unroll
    for (int p = 0; p < 2; p++) {
        int id = tid + p * 256;
        int f  = id >> 3;
        int m8 = (id & 7) * 8;
        __half tmp[8];
        #pragma unroll
        for (int k = 0; k < 8; k++) tmp[k] = T[m8 + k][f];
        *reinterpret_cast<uint4*>(dst + ((size_t)(b * Fd + fBase + f)) * Md + mBase + m8) =
            *reinterpret_cast<uint4*>(tmp);
    }
}

// =====================================================================
// Kernel 1: proj via split-fp16 mma + bias + L2 norm; hi/lo output.
// grid: (192, 8)
// =====================================================================
#define PST 72
#define PXT (128*PST)
#define PWT (64*PST)
#define PROJ_SMEM ((2*PXT + 2*PWT)*2)   // 55296 bytes

__global__ __launch_bounds__(256)
void proj_mma_kernel(const float* __restrict__ bias)
{
    extern __shared__ __half psm[];
    __half* XH = psm;
    __half* XL = XH + PXT;
    __half* WH = XL + PXT;
    __half* WL = WH + PWT;

    const int bx = blockIdx.x, h = blockIdx.y;
    const int tid = threadIdx.x;
    const int wid = tid >> 5, lane = tid & 31;
    const int r = lane >> 2, c = lane & 3;
    const int lr = lane & 7, g = lane >> 3;

    int dest, rb;
    if (bx < 32)       { dest = 0; rb = bx * 128; }
    else if (bx < 64)  { dest = 1; rb = (bx - 32) * 128; }
    else if (bx < 128) { dest = 2; rb = (bx - 64) * 128; }
    else               { dest = 3; rb = (bx - 128) * 128; }

    int srcIdx, srow;
    if (dest == 0)      { srcIdx = 0; srow = rb; }
    else if (dest == 1) { srcIdx = 1; srow = rb; }
    else if (dest == 2) { srcIdx = (rb < 4096) ? 2 : 4; srow = (rb < 4096) ? rb : rb - 4096; }
    else                { srcIdx = (rb < 4096) ? 3 : 4; srow = (rb < 4096) ? rb : rb - 4096; }

    const __half* xHi = g_XHi + (size_t)srcIdx * 4096 * 512 + (size_t)srow * 512;
    const __half* xLo = g_XLo + (size_t)srcIdx * 4096 * 512 + (size_t)srow * 512;
    const __half* wHi = g_WHi + (size_t)h * 64 * 512;
    const __half* wLo = g_WLo + (size_t)h * 64 * 512;

    __half *oHi, *oLo;
    int Lx;
    if (dest == 0)      { oHi = g_QrHi; oLo = g_QrLo; Lx = Ld; }
    else if (dest == 1) { oHi = g_QtHi; oLo = g_QtLo; Lx = Ld; }
    else if (dest == 2) { oHi = g_KrHi; oLo = g_KrLo; Lx = Md; }
    else                { oHi = g_KtHi; oLo = g_KtLo; Lx = Md; }

    const uint32_t uXH = smem_u32(XH), uXL = smem_u32(XL);
    const uint32_t uWH = smem_u32(WH), uWL = smem_u32(WL);
    const uint32_t aoff = (uint32_t)((wid*16 + lr + ((g & 1) << 3)) * PST + ((g >> 1) << 3)) * 2;
    const uint32_t boff = (uint32_t)((lr + ((g >> 1) << 3)) * PST + ((g & 1) << 3)) * 2;

    float acc[8][4] = {};

    for (int kc = 0; kc < 8; kc++) {
        const int k0 = kc * 64;
        #pragma unroll
        for (int p = 0; p < 4; p++) {
            int id = tid + p * 256;
            int row = id >> 3, seg = id & 7;
            uint32_t d = (uint32_t)(row * PST + seg * 8) * 2;
            CP_ASYNC16(uXH + d, xHi + (size_t)row * 512 + k0 + seg * 8);
            CP_ASYNC16(uXL + d, xLo + (size_t)row * 512 + k0 + seg * 8);
        }
        #pragma unroll
        for (int p = 0; p < 2; p++) {
            int id = tid + p * 256;
            int row = id >> 3, seg = id & 7;
            uint32_t d = (uint32_t)(row * PST + seg * 8) * 2;
            CP_ASYNC16(uWH + d, wHi + (size_t)row * 512 + k0 + seg * 8);
            CP_ASYNC16(uWL + d, wLo + (size_t)row * 512 + k0 + seg * 8);
        }
        CP_COMMIT();
        CP_WAIT0();
        __syncthreads();

        #pragma unroll
        for (int ks = 0; ks < 4; ks++) {
            const uint32_t ko = ks * 32;
            uint32_t ah[4], al[4];
            ldsm_x4(ah, uXH + aoff + ko);
            ldsm_x4(al, uXL + aoff + ko);
            #pragma unroll
            for (int np = 0; np < 4; np++) {
                const uint32_t no = (uint32_t)(np * 16 * PST) * 2;
                uint32_t bh[4], bl[4];
                ldsm_x4(bh, uWH + boff + no + ko);
                ldsm_x4(bl, uWL + boff + no + ko);
                #pragma unroll
                for (int hn = 0; hn < 2; hn++) {
                    int nt = np * 2 + hn;
                    uint32_t b0 = hn * 2, b1 = hn * 2 + 1;
                    mma_f16(acc[nt], ah[0], ah[1], ah[2], ah[3], bh[b0], bh[b1]);
                    mma_f16(acc[nt], ah[0], ah[1], ah[2], ah[3], bl[b0], bl[b1]);
                    mma_f16(acc[nt], al[0], al[1], al[2], al[3], bh[b0], bh[b1]);
                }
            }
        }
        __syncthreads();
    }

    #pragma unroll
    for (int nt = 0; nt < 8; nt++) {
        int col = nt * 8 + 2 * c;
        float b0 = bias[h*64 + col], b1 = bias[h*64 + col + 1];
        acc[nt][0] += b0; acc[nt][2] += b0;
        acc[nt][1] += b1; acc[nt][3] += b1;
    }

    float s0 = 0.f, s1 = 0.f;
    #pragma unroll
    for (int nt = 0; nt < 8; nt++) {
        s0 += acc[nt][0]*acc[nt][0] + acc[nt][1]*acc[nt][1];
        s1 += acc[nt][2]*acc[nt][2] + acc[nt][3]*acc[nt][3];
    }
    s0 += __shfl_xor_sync(0xffffffffu, s0, 1);
    s0 += __shfl_xor_sync(0xffffffffu, s0, 2);
    s1 += __shfl_xor_sync(0xffffffffu, s1, 1);
    s1 += __shfl_xor_sync(0xffffffffu, s1, 2);
    const float inv0 = 1.0f / fmaxf(sqrtf(s0), 1e-12f);
    const float inv1 = 1.0f / fmaxf(sqrtf(s1), 1e-12f);

    const int gr0 = rb + wid * 16 + r;
    const int gr1 = gr0 + 8;
    const int l0 = gr0 >> 2, bb0 = gr0 & 3;
    const int l1 = gr1 >> 2, bb1 = gr1 & 3;
    const size_t off0 = ((size_t)(h*4 + bb0) * Lx + l0) * 64;
    const size_t off1 = ((size_t)(h*4 + bb1) * Lx + l1) * 64;

    #pragma unroll
    for (int nt = 0; nt < 8; nt++) {
        int col = nt * 8 + 2 * c;
        float v0 = acc[nt][0] * inv0, v1 = acc[nt][1] * inv0;
        __half h0 = __float2half_rn(v0), h1 = __float2half_rn(v1);
        __half e0 = __float2half_rn(v0 - __half2float(h0));
        __half e1 = __float2half_rn(v1 - __half2float(h1));
        *reinterpret_cast<__half2*>(oHi + off0 + col) = __halves2half2(h0, h1);
        *reinterpret_cast<__half2*>(oLo + off0 + col) = __halves2half2(e0, e1);
        float w0 = acc[nt][2] * inv1, w1 = acc[nt][3] * inv1;
        __half j0 = __float2half_rn(w0), j1 = __float2half_rn(w1);
        __half f0 = __float2half_rn(w0 - __half2float(j0));
        __half f1 = __float2half_rn(w1 - __half2float(j1));
        *reinterpret_cast<__half2*>(oHi + off1 + col) = __halves2half2(j0, j1);
        *reinterpret_cast<__half2*>(oLo + off1 + col) = __halves2half2(f0, f1);
    }
}

// =====================================================================
// Kernel 2: dot via split-fp16 mma. Warp grid re-tiled 4(l) x 2(m):
// per-warp 32l x 32m -> per-ks ldsm 8A+8B (was 4A+16B = 20). Direct
// scattered STG epilogue (R11 style; R13's smem staging regressed).
// grid: (Md/64, Ld/128, HBd), block 256, dynamic smem 110592 B
// =====================================================================
#define DST 72
#define DQT (128*DST)
#define DKT (64*DST)
#define DOT_SMEM ((4*DQT + 4*DKT)*2)

__global__ __launch_bounds__(256, 2)
void dot_kernel()
{
    extern __shared__ __half dsm[];
    __half* QrH = dsm;
    __half* QrL = QrH + DQT;
    __half* QtH = QrL + DQT;
    __half* QtL = QtH + DQT;
    __half* KrH = QtL + DQT;
    __half* KrL = KrH + DKT;
    __half* KtH = KrL + DKT;
    __half* KtL = KtH + DKT;

    const int hb = blockIdx.z;
    const int mBase = blockIdx.x * 64, lBase = blockIdx.y * 128;
    const int mblk = blockIdx.x;
    const int tid = threadIdx.x;
    const int wid = tid >> 5, lane = tid & 31;
    const int wl = wid & 3, wm = wid >> 2;     // 4 l-groups x 2 m-groups
    const int r = lane >> 2, c = lane & 3;
    const int lr = lane & 7, g = lane >> 3;

    const __half* gq[4] = { g_QrHi + ((size_t)hb*Ld + lBase)*Kd, g_QrLo + ((size_t)hb*Ld + lBase)*Kd,
                            g_QtHi + ((size_t)hb*Ld + lBase)*Kd, g_QtLo + ((size_t)hb*Ld + lBase)*Kd };
    const __half* gk[4] = { g_KrHi + ((size_t)hb*Md + mBase)*Kd, g_KrLo + ((size_t)hb*Md + mBase)*Kd,
                            g_KtHi + ((size_t)hb*Md + mBase)*Kd, g_KtLo + ((size_t)hb*Md + mBase)*Kd };
    __half* sq[4] = { QrH, QrL, QtH, QtL };
    __half* sk[4] = { KrH, KrL, KtH, KtL };

    #pragma unroll
    for (int s = 0; s < 4; s++) {
        uint32_t qb = smem_u32(sq[s]);
        #pragma unroll
        for (int p = 0; p < 4; p++) {
            int id = tid + p * 256;
            int row = id >> 3, ch = id & 7;
            CP_ASYNC16(qb + (uint32_t)(row * DST + ch * 8) * 2, gq[s] + (size_t)row * Kd + ch * 8);
        }
        uint32_t kb = smem_u32(sk[s]);
        #pragma unroll
        for (int p = 0; p < 2; p++) {
            int id = tid + p * 256;
            int row = id >> 3, ch = id & 7;
            CP_ASYNC16(kb + (uint32_t)(row * DST + ch * 8) * 2, gk[s] + (size_t)row * Kd + ch * 8);
        }
    }
    CP_COMMIT();
    CP_WAIT0();
    __syncthreads();

    float accR[2][4][4] = {}, accT[2][4][4] = {};   // [af][nt][reg]

    uint32_t aoff[2];
    #pragma unroll
    for (int af = 0; af < 2; af++)
        aoff[af] = (uint32_t)((wl*32 + af*16 + lr + ((g & 1) << 3)) * DST + ((g >> 1) << 3)) * 2;
    const uint32_t boff = (uint32_t)((wm*32 + lr + ((g >> 1) << 3)) * DST + ((g & 1) << 3)) * 2;
    const uint32_t uQrH = smem_u32(QrH), uQrL = smem_u32(QrL);
    const uint32_t uQtH = smem_u32(QtH), uQtL = smem_u32(QtL);
    const uint32_t uKrH = smem_u32(KrH), uKrL = smem_u32(KrL);
    const uint32_t uKtH = smem_u32(KtH), uKtL = smem_u32(KtL);

    #pragma unroll
    for (int ks = 0; ks < 4; ks++) {
        const uint32_t ko = ks * 32;
        // ---- stream R ----
        {
            uint32_t qh[2][4], ql[2][4];
            ldsm_x4(qh[0], uQrH + aoff[0] + ko);
            ldsm_x4(qh[1], uQrH + aoff[1] + ko);
            ldsm_x4(ql[0], uQrL + aoff[0] + ko);
            ldsm_x4(ql[1], uQrL + aoff[1] + ko);
            #pragma unroll
            for (int np = 0; np < 2; np++) {
                const uint32_t no = (uint32_t)(np * 16 * DST) * 2;
                uint32_t kh[4], kl[4];
                ldsm_x4(kh, uKrH + boff + no + ko);
                ldsm_x4(kl, uKrL + boff + no + ko);
                #pragma unroll
                for (int af = 0; af < 2; af++)
                    #pragma unroll
                    for (int hn = 0; hn < 2; hn++) {
                        int nt = np * 2 + hn;
                        uint32_t b0 = hn * 2, b1 = hn * 2 + 1;
                        mma_f16(accR[af][nt], qh[af][0], qh[af][1], qh[af][2], qh[af][3], kh[b0], kh[b1]);
                        mma_f16(accR[af][nt], qh[af][0], qh[af][1], qh[af][2], qh[af][3], kl[b0], kl[b1]);
                        mma_f16(accR[af][nt], ql[af][0], ql[af][1], ql[af][2], ql[af][3], kh[b0], kh[b1]);
                    }
            }
        }
        // ---- stream T ----
        {
            uint32_t qh[2][4], ql[2][4];
            ldsm_x4(qh[0], uQtH + aoff[0] + ko);
            ldsm_x4(qh[1], uQtH + aoff[1] + ko);
            ldsm_x4(ql[0], uQtL + aoff[0] + ko);
            ldsm_x4(ql[1], uQtL + aoff[1] + ko);
            #pragma unroll
            for (int np = 0; np < 2; np++) {
                const uint32_t no = (uint32_t)(np * 16 * DST) * 2;
                uint32_t kh[4], kl[4];
                ldsm_x4(kh, uKtH + boff + no + ko);
                ldsm_x4(kl, uKtL + boff + no + ko);
                #pragma unroll
                for (int af = 0; af < 2; af++)
                    #pragma unroll
                    for (int hn = 0; hn < 2; hn++) {
                        int nt = np * 2 + hn;
                        uint32_t b0 = hn * 2, b1 = hn * 2 + 1;
                        mma_f16(accT[af][nt], qh[af][0], qh[af][1], qh[af][2], qh[af][3], kh[b0], kh[b1]);
                        mma_f16(accT[af][nt], qh[af][0], qh[af][1], qh[af][2], qh[af][3], kl[b0], kl[b1]);
                        mma_f16(accT[af][nt], ql[af][0], ql[af][1], ql[af][2], ql[af][3], kh[b0], kh[b1]);
                    }
            }
        }
    }

    // ---- epilogue: direct scattered STG (proven) + partial maxes ----
    float pm[3][2][2];   // [stream][af][half]
    #pragma unroll
    for (int s = 0; s < 3; s++)
        #pragma unroll
        for (int af = 0; af < 2; af++) { pm[s][af][0] = -1e30f; pm[s][af][1] = -1e30f; }

    #pragma unroll
    for (int af = 0; af < 2; af++) {
        const int lrow0 = lBase + wl*32 + af*16 + r;
        float* sR0 = g_Srgb + ((size_t)hb * Ld + lrow0) * Md + mBase + wm*32;
        float* sR1 = sR0 + 8 * Md;
        float* sT0 = g_St   + ((size_t)hb * Ld + lrow0) * Md + mBase + wm*32;
        float* sT1 = sT0 + 8 * Md;
        #pragma unroll
        for (int nt = 0; nt < 4; nt++) {
            int col = nt * 8 + 2 * c;
            *reinterpret_cast<float2*>(sR0 + col) = make_float2(accR[af][nt][0], accR[af][nt][1]);
            *reinterpret_cast<float2*>(sR1 + col) = make_float2(accR[af][nt][2], accR[af][nt][3]);
            *reinterpret_cast<float2*>(sT0 + col) = make_float2(accT[af][nt][0], accT[af][nt][1]);
            *reinterpret_cast<float2*>(sT1 + col) = make_float2(accT[af][nt][2], accT[af][nt][3]);
            pm[0][af][0] = fmaxf(pm[0][af][0], fmaxf(accR[af][nt][0], accR[af][nt][1]));
            pm[0][af][1] = fmaxf(pm[0][af][1], fmaxf(accR[af][nt][2], accR[af][nt][3]));
            pm[1][af][0] = fmaxf(pm[1][af][0], fmaxf(accT[af][nt][0], accT[af][nt][1]));
            pm[1][af][1] = fmaxf(pm[1][af][1], fmaxf(accT[af][nt][2], accT[af][nt][3]));
            pm[2][af][0] = fmaxf(pm[2][af][0], fmaxf(accR[af][nt][0]*accT[af][nt][0],
                                                     accR[af][nt][1]*accT[af][nt][1]));
            pm[2][af][1] = fmaxf(pm[2][af][1], fmaxf(accR[af][nt][2]*accT[af][nt][2],
                                                     accR[af][nt][3]*accT[af][nt][3]));
        }
    }
    #pragma unroll
    for (int s = 0; s < 3; s++)
        #pragma unroll
        for (int af = 0; af < 2; af++)
            #pragma unroll
            for (int hf = 0; hf < 2; hf++) {
                pm[s][af][hf] = fmaxf(pm[s][af][hf], __shfl_xor_sync(0xffffffffu, pm[s][af][hf], 1));
                pm[s][af][hf] = fmaxf(pm[s][af][hf], __shfl_xor_sync(0xffffffffu, pm[s][af][hf], 2));
            }
    if (c == 0) {
        #pragma unroll
        for (int af = 0; af < 2; af++)
            #pragma unroll
            for (int hf = 0; hf < 2; hf++) {
                size_t row = (size_t)hb * Ld + lBase + wl*32 + af*16 + r + hf*8;
                int slot = mblk * 2 + wm;
                g_pmax[row*192 +       slot] = pm[0][af][hf];
                g_pmax[row*192 +  64 + slot] = pm[1][af][hf];
                g_pmax[row*192 + 128 + slot] = pm[2][af][hf];
            }
    }
}

// =====================================================================
// Kernel 3: stats — reduce 64 partial-max slots, one pass ex2.f16x2.
// =====================================================================
__global__ __launch_bounds__(256)
void stats_kernel()
{
    const int row = blockIdx.x;
    const float* sr = g_Srgb + (size_t)row * Md;
    const float* st = g_St   + (size_t)row * Md;
    __half* pr = g_PrH + (size_t)row * Md;
    __half* pt = g_PtH + (size_t)row * Md;
    __half* px = g_PxH + (size_t)row * Md;
    const int tid = threadIdx.x;
    const int lane = tid & 31, wid = tid >> 5;
    __shared__ float smax[3];
    __shared__ float sm[8][3];

    if (wid < 3) {
        float v = fmaxf(g_pmax[(size_t)row * 192 + wid*64 + lane],
                        g_pmax[(size_t)row * 192 + wid*64 + 32 + lane]);
        #pragma unroll
        for (int o = 16; o > 0; o >>= 1)
            v = fmaxf(v, __shfl_xor_sync(0xffffffffu, v, o));
        if (lane == 0) smax[wid] = v;
    }
    __syncthreads();

    const float L2E = 1.44269504088896340736f;
    const float m1 = 100.f * smax[0], m2 = 100.f * smax[1], m3 = smax[2];
    const float c100 = 100.f * L2E;
    const float mm1 = m1 * L2E, mm2 = m2 * L2E, mm3 = m3 * L2E;

    float s1 = 0.f, s2 = 0.f, s3 = 0.f;
    #pragma unroll
    for (int it = 0; it < 2; it++) {
        int i = (tid + it * 256) * 4;
        float4 a = *reinterpret_cast<const float4*>(sr + i);
        float4 b = *reinterpret_cast<const float4*>(st + i);

        uint32_t u0 = h2exp2u(pack_h2(fmaf(c100, a.x, -mm1), fmaf(c100, a.y, -mm1)));
        uint32_t u1 = h2exp2u(pack_h2(fmaf(c100, a.z, -mm1), fmaf(c100, a.w, -mm1)));
        *reinterpret_cast<uint2*>(pr + i) = make_uint2(u0, u1);
        float2 f0 = h2f2(u0), f1 = h2f2(u1);
        s1 += (f0.x + f0.y) + (f1.x + f1.y);

        u0 = h2exp2u(pack_h2(fmaf(c100, b.x, -mm2), fmaf(c100, b.y, -mm2)));
        u1 = h2exp2u(pack_h2(fmaf(c100, b.z, -mm2), fmaf(c100, b.w, -mm2)));
        *reinterpret_cast<uint2*>(pt + i) = make_uint2(u0, u1);
        f0 = h2f2(u0); f1 = h2f2(u1);
        s2 += (f0.x + f0.y) + (f1.x + f1.y);

        u0 = h2exp2u(pack_h2(fmaf(L2E, a.x*b.x, -mm3), fmaf(L2E, a.y*b.y, -mm3)));
        u1 = h2exp2u(pack_h2(fmaf(L2E, a.z*b.z, -mm3), fmaf(L2E, a.w*b.w, -mm3)));
        *reinterpret_cast<uint2*>(px + i) = make_uint2(u0, u1);
        f0 = h2f2(u0); f1 = h2f2(u1);
        s3 += (f0.x + f0.y) + (f1.x + f1.y);
    }
    #pragma unroll
    for (int o = 16; o > 0; o >>= 1) {
        s1 += __shfl_xor_sync(0xffffffffu, s1, o);
        s2 += __shfl_xor_sync(0xffffffffu, s2, o);
        s3 += __shfl_xor_sync(0xffffffffu, s3, o);
    }
    if (lane == 0) { sm[wid][0] = s1; sm[wid][1] = s2; sm[wid][2] = s3; }
    __syncthreads();
    if (tid == 0) {
        s1 = s2 = s3 = 0.f;
        #pragma unroll
        for (int w = 0; w < 8; w++) { s1 += sm[w][0]; s2 += sm[w][1]; s3 += sm[w][2]; }
        float* o = g_stats + (size_t)row * 6;
        o[0] = m1; o[1] = s1; o[2] = m2; o[3] = s2; o[4] = m3; o[5] = s3;
    }
}

// =====================================================================
// Kernel 4: attend — fp16 mma, tile 64l x 128f, 2-stage cp.async double
// buffer. 8 warps = 2(l) x 4(f), each 32x32. (unchanged from R11)
// grid: (F/128, L/64, HB), block 256, dynamic smem 71680 B
// =====================================================================
#define AST    40
#define PTILE  (64*AST)             // 2560 halves per P tile
#define VTILE  (128*AST)            // 5120 halves per V tile
#define ASTG   (3*PTILE + 2*VTILE)  // 17920 halves per stage
#define ATT_SMEM (2*ASTG*2)         // 71680 bytes
#define NCHUNK (Md/32)              // 64

__global__ __launch_bounds__(256, 1)
void attend_mma_kernel(float* __restrict__ out)
{
    extern __shared__ __half ash[];
    const int hb = blockIdx.z;
    const int h  = hb / Bd, b = hb % Bd;
    const int fBase = blockIdx.x * 128, lBase = blockIdx.y * 64;
    const int tid = threadIdx.x;
    const int wid = tid >> 5, lane = tid & 31;
    const int wl = wid & 1, wf = wid >> 1;     // 2 l-groups x 4 f-groups
    const int r = lane >> 2, c = lane & 3;
    const int lr = lane & 7, g = lane >> 3;

    const __half* s0 = g_PrH + ((size_t)hb * Ld + lBase) * Md;
    const __half* s1 = g_PtH + ((size_t)hb * Ld + lBase) * Md;
    const __half* s2 = g_PxH + ((size_t)hb * Ld + lBase) * Md;
    const __half* s3 = g_VrT + ((size_t)(b * Fd + fBase)) * Md;
    const __half* s4 = g_VtT + ((size_t)(b * Fd + fBase)) * Md;

    const uint32_t sbase = smem_u32(ash);
    const int prow = tid >> 2, pseg = tid & 3;               // 64 rows x 4 16B-segs
    const uint32_t dP  = (uint32_t)(prow * AST + pseg * 8) * 2;
    const uint32_t dV0 = dP;                                  // V row prow
    const uint32_t dV1 = (uint32_t)((prow + 64) * AST + pseg * 8) * 2;
    const size_t gP  = (size_t)prow * Md + pseg * 8;
    const size_t gV1 = (size_t)(prow + 64) * Md + pseg * 8;

    // ldmatrix fragment offsets within a stage (bytes)
    uint32_t aoff[2];
    #pragma unroll
    for (int af = 0; af < 2; af++)
        aoff[af] = (uint32_t)((wl*32 + af*16 + lr + ((g & 1) << 3)) * AST + ((g >> 1) << 3)) * 2;
    const uint32_t boff = (uint32_t)((wf*32 + lr + ((g >> 1) << 3)) * AST + ((g & 1) << 3)) * 2;

    float acc[4][2][4][4] = {};   // [out][afrag][ntile][reg]

    // prologue: stage 0 <- chunk 0
    {
        uint32_t st = sbase;
        CP_ASYNC16(st + 0*PTILE*2 + dP, s0 + gP);
        CP_ASYNC16(st + 1*PTILE*2 + dP, s1 + gP);
        CP_ASYNC16(st + 2*PTILE*2 + dP, s2 + gP);
        CP_ASYNC16(st + 3*PTILE*2 + dV0, s3 + gP);
        CP_ASYNC16(st + 3*PTILE*2 + dV1, s3 + gV1);
        CP_ASYNC16(st + (3*PTILE + VTILE)*2 + dV0, s4 + gP);
        CP_ASYNC16(st + (3*PTILE + VTILE)*2 + dV1, s4 + gV1);
    }
    CP_COMMIT();

    for (int cc = 0; cc < NCHUNK; cc++) {
        if (cc + 1 < NCHUNK) {
            size_t o1 = (size_t)(cc + 1) * 32;
            uint32_t st = sbase + (uint32_t)(((cc + 1) & 1) * ASTG) * 2;
            CP_ASYNC16(st + 0*PTILE*2 + dP, s0 + gP + o1);
            CP_ASYNC16(st + 1*PTILE*2 + dP, s1 + gP + o1);
            CP_ASYNC16(st + 2*PTILE*2 + dP, s2 + gP + o1);
            CP_ASYNC16(st + 3*PTILE*2 + dV0, s3 + gP + o1);
            CP_ASYNC16(st + 3*PTILE*2 + dV1, s3 + gV1 + o1);
            CP_ASYNC16(st + (3*PTILE + VTILE)*2 + dV0, s4 + gP + o1);
            CP_ASYNC16(st + (3*PTILE + VTILE)*2 + dV1, s4 + gV1 + o1);
        }
        CP_COMMIT();
        CP_WAIT1();
        __syncthreads();

        const uint32_t stg = sbase + (uint32_t)((cc & 1) * ASTG) * 2;
        const uint32_t uPr = stg;
        const uint32_t uPt = stg + 1*PTILE*2;
        const uint32_t uPx = stg + 2*PTILE*2;
        const uint32_t uVr = stg + 3*PTILE*2;
        const uint32_t uVt = stg + (3*PTILE + VTILE)*2;

        #pragma unroll
        for (int ks = 0; ks < 2; ks++) {
            const uint32_t ko = ks * 32;
            uint32_t ar[2][4], at[2][4], ax[2][4];
            #pragma unroll
            for (int af = 0; af < 2; af++) {
                ldsm_x4(ar[af], uPr + aoff[af] + ko);
                ldsm_x4(at[af], uPt + aoff[af] + ko);
                ldsm_x4(ax[af], uPx + aoff[af] + ko);
            }
            #pragma unroll
            for (int np = 0; np < 2; np++) {
                const uint32_t no = (uint32_t)(np * 16 * AST) * 2;
                uint32_t vr[4], vt[4];
                ldsm_x4(vr, uVr + boff + no + ko);
                ldsm_x4(vt, uVt + boff + no + ko);
                #pragma unroll
                for (int af = 0; af < 2; af++) {
                    #pragma unroll
                    for (int hn = 0; hn < 2; hn++) {
                        int nt = np * 2 + hn;
                        uint32_t b0 = hn * 2, b1 = hn * 2 + 1;
                        mma_f16(acc[0][af][nt], ar[af][0], ar[af][1], ar[af][2], ar[af][3], vr[b0], vr[b1]);
                        mma_f16(acc[1][af][nt], at[af][0], at[af][1], at[af][2], at[af][3], vt[b0], vt[b1]);
                        mma_f16(acc[2][af][nt], ax[af][0], ax[af][1], ax[af][2], ax[af][3], vt[b0], vt[b1]);
                        mma_f16(acc[3][af][nt], ax[af][0], ax[af][1], ax[af][2], ax[af][3], vr[b0], vr[b1]);
                    }
                }
            }
        }
        __syncthreads();
    }

    const size_t OSZ = (size_t)Ld * Bd * HFd;
    #pragma unroll
    for (int af = 0; af < 2; af++) {
        const int l0 = lBase + wl * 32 + af * 16 + r;
        const int l1 = l0 + 8;
        const float* st0 = g_stats + ((size_t)hb * Ld + l0) * 6;
        const float* st1 = g_stats + ((size_t)hb * Ld + l1) * 6;
        const float inv0[4] = {1.f/st0[1], 1.f/st0[3], 1.f/st0[5], 1.f/st0[5]};
        const float inv1[4] = {1.f/st1[1], 1.f/st1[3], 1.f/st1[5], 1.f/st1[5]};
        const size_t base0 = ((size_t)l0 * Bd + b) * HFd + (size_t)h * Fd;
        const size_t base1 = ((size_t)l1 * Bd + b) * HFd + (size_t)h * Fd;
        #pragma unroll
        for (int d = 0; d < 4; d++) {
            #pragma unroll
            for (int nt = 0; nt < 4; nt++) {
                int f = fBase + wf * 32 + nt * 8 + 2 * c;
                *reinterpret_cast<float2*>(out + d*OSZ + base0 + f) =
                    make_float2(acc[d][af][nt][0] * inv0[d], acc[d][af][nt][1] * inv0[d]);
                *reinterpret_cast<float2*>(out + d*OSZ + base1 + f) =
                    make_float2(acc[d][af][nt][2] * inv1[d], acc[d][af][nt][3] * inv1[d]);
            }
        }
    }
}

// =====================================================================
extern "C" void kernel_launch(void* const* d_in, const int* in_sizes, int n_in,
                              void* d_out, int out_size)
{
    const float* rgbquery  = (const float*)d_in[0];
    const float* rgbkey    = (const float*)d_in[1];
    const float* rgbvalue  = (const float*)d_in[2];
    const float* tquery    = (const float*)d_in[3];
    const float* tkey      = (const float*)d_in[4];
    const float* tvalue    = (const float*)d_in[5];
    const float* fusekey   = (const float*)d_in[6];
    const float* fusevalue = (const float*)d_in[7];
    const float* WK_w      = (const float*)d_in[8];
    const float* WK_b      = (const float*)d_in[9];
    float* out = (float*)d_out;

    cudaFuncSetAttribute(proj_mma_kernel, cudaFuncAttributeMaxDynamicSharedMemorySize, PROJ_SMEM);
    cudaFuncSetAttribute(dot_kernel, cudaFuncAttributeMaxDynamicSharedMemorySize, DOT_SMEM);
    cudaFuncSetAttribute(attend_mma_kernel, cudaFuncAttributeMaxDynamicSharedMemorySize, ATT_SMEM);

    split_kernel<<<dim3(1024, 6), 256>>>(rgbquery, tquery, rgbkey, tkey, fusekey, WK_w);
    vtrans_kernel<<<dim3(Md/64, Fd/64, Bd*2), 256>>>(rgbvalue, tvalue, fusevalue);
    proj_mma_kernel<<<dim3(192, Hd), 256, PROJ_SMEM>>>(WK_b);
    dot_kernel<<<dim3(Md/64, Ld/128, HBd), 256, DOT_SMEM>>>();
    stats_kernel<<<HBd*Ld, 256>>>();
    attend_mma_kernel<<<dim3(Fd/128, Ld/64, HBd), 256, ATT_SMEM>>>(out);
}

// round 17
// speedup vs baseline: 1.1200x; 1.0171x over previous
#include <cuda_runtime.h>
#include <cuda_fp16.h>
#include <cstdint>
#include <math.h>

// Problem constants
#define Ld  1024
#define Bd  4
#define Fd  512
#define Hd  8
#define Kd  64
#define Md  2048          // Lk + Lfuse
#define HBd (Hd*Bd)       // 32
#define HFd (Hd*Fd)       // 4096

// ---------------- scratch (device globals; no allocs allowed) ----------------
__device__ __half g_XHi[(size_t)5*4096*512], g_XLo[(size_t)5*4096*512]; // inputs split
__device__ __half g_WHi[512*512], g_WLo[512*512];                       // WK_w split
__device__ __half g_QrHi[HBd*Ld*Kd], g_QrLo[HBd*Ld*Kd];   // Q/K in split fp16
__device__ __half g_QtHi[HBd*Ld*Kd], g_QtLo[HBd*Ld*Kd];
__device__ __half g_KrHi[HBd*Md*Kd], g_KrLo[HBd*Md*Kd];
__device__ __half g_KtHi[HBd*Md*Kd], g_KtLo[HBd*Md*Kd];
__device__ float  g_Srgb[(size_t)HBd*Ld*Md];     // raw dots (fp32)
__device__ float  g_St  [(size_t)HBd*Ld*Md];
__device__ __half g_PrH[(size_t)HBd*Ld*Md];      // unnormalized softmax numerators (half)
__device__ __half g_PtH[(size_t)HBd*Ld*Md];
__device__ __half g_PxH[(size_t)HBd*Ld*Md];
__device__ __half g_VrT[(size_t)Bd*Fd*Md];       // V^T half: [b][f][m]
__device__ __half g_VtT[(size_t)Bd*Fd*Md];
__device__ float  g_pmax[(size_t)HBd*Ld*96];     // per-row partial maxes [3][32 slots]
__device__ float  g_stats[HBd*Ld*6];

// ---------------- mma / ldmatrix / exp2 / cp.async helpers ----------------
__device__ __forceinline__ void mma_f16(float* c,
                                        uint32_t a0, uint32_t a1, uint32_t a2, uint32_t a3,
                                        uint32_t b0, uint32_t b1) {
    asm volatile(
        "mma.sync.aligned.m16n8k16.row.col.f32.f16.f16.f32 "
        "{%0,%1,%2,%3}, {%4,%5,%6,%7}, {%8,%9}, {%0,%1,%2,%3};"
        : "+f"(c[0]), "+f"(c[1]), "+f"(c[2]), "+f"(c[3])
        : "r"(a0), "r"(a1), "r"(a2), "r"(a3), "r"(b0), "r"(b1));
}
__device__ __forceinline__ void ldsm_x4(uint32_t* r, uint32_t addr) {
    asm volatile("ldmatrix.sync.aligned.m8n8.x4.shared.b16 {%0,%1,%2,%3}, [%4];"
                 : "=r"(r[0]), "=r"(r[1]), "=r"(r[2]), "=r"(r[3]) : "r"(addr));
}
__device__ __forceinline__ uint32_t h2exp2u(uint32_t x) {
    uint32_t r; asm("ex2.approx.f16x2 %0, %1;" : "=r"(r) : "r"(x)); return r;
}
__device__ __forceinline__ uint32_t pack_h2(float a, float b) {
    __half2 h = __floats2half2_rn(a, b);
    return *reinterpret_cast<uint32_t*>(&h);
}
__device__ __forceinline__ float2 h2f2(uint32_t u) {
    __half2 h = *reinterpret_cast<__half2*>(&u);
    return __half22float2(h);
}
__device__ __forceinline__ uint32_t smem_u32(const void* p) {
    uint32_t a;
    asm("{ .reg .u64 t; cvta.to.shared.u64 t, %1; cvt.u32.u64 %0, t; }" : "=r"(a) : "l"(p));
    return a;
}
#define CP_ASYNC16(dst, src) \
    asm volatile("cp.async.ca.shared.global [%0], [%1], 16;" :: "r"(dst), "l"(src) : "memory")
#define CP_COMMIT() asm volatile("cp.async.commit_group;" ::: "memory")
#define CP_WAIT1()  asm volatile("cp.async.wait_group 1;" ::: "memory")
#define CP_WAIT0()  asm volatile("cp.async.wait_group 0;" ::: "memory")

// =====================================================================
// Kernel A: split inputs + W into fp16 hi/lo pairs.
// grid: (1024, 6), block 256. y=0..4 -> X sources (4096x512), y=5 -> W.
// =====================================================================
__global__ __launch_bounds__(256)
void split_kernel(const float* __restrict__ q0, const float* __restrict__ q1,
                  const float* __restrict__ k0p, const float* __restrict__ k1p,
                  const float* __restrict__ kf,  const float* __restrict__ w)
{
    const int y = blockIdx.y;
    const float* srcs[6] = {q0, q1, k0p, k1p, kf, w};
    const float* src = srcs[y];
    const int N = (y == 5) ? (512*512) : (4096*512);
    const int el = (blockIdx.x * 256 + threadIdx.x) * 8;
    if (el >= N) return;
    __half* dHi = (y == 5) ? g_WHi : g_XHi + (size_t)y * 4096 * 512;
    __half* dLo = (y == 5) ? g_WLo : g_XLo + (size_t)y * 4096 * 512;

    float4 a = *reinterpret_cast<const float4*>(src + el);
    float4 b = *reinterpret_cast<const float4*>(src + el + 4);
    float v[8] = {a.x, a.y, a.z, a.w, b.x, b.y, b.z, b.w};
    __half hh[8], hl[8];
    #pragma unroll
    for (int i = 0; i < 8; i++) {
        hh[i] = __float2half_rn(v[i]);
        hl[i] = __float2half_rn(v[i] - __half2float(hh[i]));
    }
    *reinterpret_cast<uint4*>(dHi + el) = *reinterpret_cast<uint4*>(hh);
    *reinterpret_cast<uint4*>(dLo + el) = *reinterpret_cast<uint4*>(hl);
}

// =====================================================================
// Kernel 0: V transpose+convert -> half [b][f][m]
// =====================================================================
__global__ __launch_bounds__(256)
void vtrans_kernel(const float* __restrict__ rgbvalue,
                   const float* __restrict__ tvalue,
                   const float* __restrict__ fusevalue)
{
    __shared__ __half T[64][66];
    const int mBase = blockIdx.x * 64, fBase = blockIdx.y * 64;
    const int b = blockIdx.z & 3, sel = blockIdx.z >> 2;
    const float* v0 = sel ? tvalue : rgbvalue;
    __half* dst = sel ? g_VtT : g_VrT;
    const int tid = threadIdx.x;

    #pragma unroll
    for (int p = 0; p < 2; p++) {
        int id = tid + p * 256;
        int m  = id >> 3;
        int f8 = (id & 7) * 8;
        int mm = mBase + m;
        const float* src = (mm < Ld) ? v0 + ((size_t)mm * Bd + b) * Fd
                                     : fusevalue + ((size_t)(mm - Ld) * Bd + b) * Fd;
        float4 x = *reinterpret_cast<const float4*>(src + fBase + f8);
        float4 y = *reinterpret_cast<const float4*>(src + fBase + f8 + 4);
        T[m][f8+0] = __float2half(x.x); T[m][f8+1] = __float2half(x.y);
        T[m][f8+2] = __float2half(x.z); T[m][f8+3] = __float2half(x.w);
        T[m][f8+4] = __float2half(y.x); T[m][f8+5] = __float2half(y.y);
        T[m][f8+6] = __float2half(y.z); T[m][f8+7] = __float2half(y.w);
    }
    __syncthreads();
    #pragma unroll
    for (int p = 0; p < 2; p++) {
        int id = tid + p * 256;
        int f  = id >> 3;
        int m8 = (id & 7) * 8;
        __half tmp[8];
        #pragma unroll
        for (int k = 0; k < 8; k++) tmp[k] = T[m8 + k][f];
        *reinterpret_cast<uint4*>(dst + ((size_t)(b * Fd + fBase + f)) * Md + mBase + m8) =
            *reinterpret_cast<uint4*>(tmp);
    }
}

// =====================================================================
// Kernel 1: proj via split-fp16 mma + bias + L2 norm; hi/lo output.
// grid: (192, 8)
// =====================================================================
#define PST 72
#define PXT (128*PST)
#define PWT (64*PST)
#define PROJ_SMEM ((2*PXT + 2*PWT)*2)   // 55296 bytes

__global__ __launch_bounds__(256)
void proj_mma_kernel(const float* __restrict__ bias)
{
    extern __shared__ __half psm[];
    __half* XH = psm;
    __half* XL = XH + PXT;
    __half* WH = XL + PXT;
    __half* WL = WH + PWT;

    const int bx = blockIdx.x, h = blockIdx.y;
    const int tid = threadIdx.x;
    const int wid = tid >> 5, lane = tid & 31;
    const int r = lane >> 2, c = lane & 3;
    const int lr = lane & 7, g = lane >> 3;

    int dest, rb;
    if (bx < 32)       { dest = 0; rb = bx * 128; }
    else if (bx < 64)  { dest = 1; rb = (bx - 32) * 128; }
    else if (bx < 128) { dest = 2; rb = (bx - 64) * 128; }
    else               { dest = 3; rb = (bx - 128) * 128; }

    int srcIdx, srow;
    if (dest == 0)      { srcIdx = 0; srow = rb; }
    else if (dest == 1) { srcIdx = 1; srow = rb; }
    else if (dest == 2) { srcIdx = (rb < 4096) ? 2 : 4; srow = (rb < 4096) ? rb : rb - 4096; }
    else                { srcIdx = (rb < 4096) ? 3 : 4; srow = (rb < 4096) ? rb : rb - 4096; }

    const __half* xHi = g_XHi + (size_t)srcIdx * 4096 * 512 + (size_t)srow * 512;
    const __half* xLo = g_XLo + (size_t)srcIdx * 4096 * 512 + (size_t)srow * 512;
    const __half* wHi = g_WHi + (size_t)h * 64 * 512;
    const __half* wLo = g_WLo + (size_t)h * 64 * 512;

    __half *oHi, *oLo;
    int Lx;
    if (dest == 0)      { oHi = g_QrHi; oLo = g_QrLo; Lx = Ld; }
    else if (dest == 1) { oHi = g_QtHi; oLo = g_QtLo; Lx = Ld; }
    else if (dest == 2) { oHi = g_KrHi; oLo = g_KrLo; Lx = Md; }
    else                { oHi = g_KtHi; oLo = g_KtLo; Lx = Md; }

    const uint32_t uXH = smem_u32(XH), uXL = smem_u32(XL);
    const uint32_t uWH = smem_u32(WH), uWL = smem_u32(WL);
    const uint32_t aoff = (uint32_t)((wid*16 + lr + ((g & 1) << 3)) * PST + ((g >> 1) << 3)) * 2;
    const uint32_t boff = (uint32_t)((lr + ((g >> 1) << 3)) * PST + ((g & 1) << 3)) * 2;

    float acc[8][4] = {};

    for (int kc = 0; kc < 8; kc++) {
        const int k0 = kc * 64;
        #pragma unroll
        for (int p = 0; p < 4; p++) {
            int id = tid + p * 256;
            int row = id >> 3, seg = id & 7;
            uint32_t d = (uint32_t)(row * PST + seg * 8) * 2;
            CP_ASYNC16(uXH + d, xHi + (size_t)row * 512 + k0 + seg * 8);
            CP_ASYNC16(uXL + d, xLo + (size_t)row * 512 + k0 + seg * 8);
        }
        #pragma unroll
        for (int p = 0; p < 2; p++) {
            int id = tid + p * 256;
            int row = id >> 3, seg = id & 7;
            uint32_t d = (uint32_t)(row * PST + seg * 8) * 2;
            CP_ASYNC16(uWH + d, wHi + (size_t)row * 512 + k0 + seg * 8);
            CP_ASYNC16(uWL + d, wLo + (size_t)row * 512 + k0 + seg * 8);
        }
        CP_COMMIT();
        CP_WAIT0();
        __syncthreads();

        #pragma unroll
        for (int ks = 0; ks < 4; ks++) {
            const uint32_t ko = ks * 32;
            uint32_t ah[4], al[4];
            ldsm_x4(ah, uXH + aoff + ko);
            ldsm_x4(al, uXL + aoff + ko);
            #pragma unroll
            for (int np = 0; np < 4; np++) {
                const uint32_t no = (uint32_t)(np * 16 * PST) * 2;
                uint32_t bh[4], bl[4];
                ldsm_x4(bh, uWH + boff + no + ko);
                ldsm_x4(bl, uWL + boff + no + ko);
                #pragma unroll
                for (int hn = 0; hn < 2; hn++) {
                    int nt = np * 2 + hn;
                    uint32_t b0 = hn * 2, b1 = hn * 2 + 1;
                    mma_f16(acc[nt], ah[0], ah[1], ah[2], ah[3], bh[b0], bh[b1]);
                    mma_f16(acc[nt], ah[0], ah[1], ah[2], ah[3], bl[b0], bl[b1]);
                    mma_f16(acc[nt], al[0], al[1], al[2], al[3], bh[b0], bh[b1]);
                }
            }
        }
        __syncthreads();
    }

    #pragma unroll
    for (int nt = 0; nt < 8; nt++) {
        int col = nt * 8 + 2 * c;
        float b0 = bias[h*64 + col], b1 = bias[h*64 + col + 1];
        acc[nt][0] += b0; acc[nt][2] += b0;
        acc[nt][1] += b1; acc[nt][3] += b1;
    }

    float s0 = 0.f, s1 = 0.f;
    #pragma unroll
    for (int nt = 0; nt < 8; nt++) {
        s0 += acc[nt][0]*acc[nt][0] + acc[nt][1]*acc[nt][1];
        s1 += acc[nt][2]*acc[nt][2] + acc[nt][3]*acc[nt][3];
    }
    s0 += __shfl_xor_sync(0xffffffffu, s0, 1);
    s0 += __shfl_xor_sync(0xffffffffu, s0, 2);
    s1 += __shfl_xor_sync(0xffffffffu, s1, 1);
    s1 += __shfl_xor_sync(0xffffffffu, s1, 2);
    const float inv0 = 1.0f / fmaxf(sqrtf(s0), 1e-12f);
    const float inv1 = 1.0f / fmaxf(sqrtf(s1), 1e-12f);

    const int gr0 = rb + wid * 16 + r;
    const int gr1 = gr0 + 8;
    const int l0 = gr0 >> 2, bb0 = gr0 & 3;
    const int l1 = gr1 >> 2, bb1 = gr1 & 3;
    const size_t off0 = ((size_t)(h*4 + bb0) * Lx + l0) * 64;
    const size_t off1 = ((size_t)(h*4 + bb1) * Lx + l1) * 64;

    #pragma unroll
    for (int nt = 0; nt < 8; nt++) {
        int col = nt * 8 + 2 * c;
        float v0 = acc[nt][0] * inv0, v1 = acc[nt][1] * inv0;
        __half h0 = __float2half_rn(v0), h1 = __float2half_rn(v1);
        __half e0 = __float2half_rn(v0 - __half2float(h0));
        __half e1 = __float2half_rn(v1 - __half2float(h1));
        *reinterpret_cast<__half2*>(oHi + off0 + col) = __halves2half2(h0, h1);
        *reinterpret_cast<__half2*>(oLo + off0 + col) = __halves2half2(e0, e1);
        float w0 = acc[nt][2] * inv1, w1 = acc[nt][3] * inv1;
        __half j0 = __float2half_rn(w0), j1 = __float2half_rn(w1);
        __half f0 = __float2half_rn(w0 - __half2float(j0));
        __half f1 = __float2half_rn(w1 - __half2float(j1));
        *reinterpret_cast<__half2*>(oHi + off1 + col) = __halves2half2(j0, j1);
        *reinterpret_cast<__half2*>(oLo + off1 + col) = __halves2half2(f0, f1);
    }
}

// =====================================================================
// Kernel 2: dot via split-fp16 mma. Tile 128l x 128m (traffic -33%),
// loads in TWO commit groups: R operands then T operands; R compute
// overlaps T loads. 8 warps = 4(l) x 2(m), each 32l x 64m.
// grid: (Md/128, Ld/128, HBd), block 256, dynamic smem 147456 B
// =====================================================================
#define DST 72
#define DQT (128*DST)
#define DKT (128*DST)
#define DOT_SMEM ((4*DQT + 4*DKT)*2)   // 147456 bytes

__global__ __launch_bounds__(256, 1)
void dot_kernel()
{
    extern __shared__ __half dsm[];
    __half* QrH = dsm;
    __half* QrL = QrH + DQT;
    __half* KrH = QrL + DQT;
    __half* KrL = KrH + DKT;
    __half* QtH = KrL + DKT;
    __half* QtL = QtH + DQT;
    __half* KtH = QtL + DQT;
    __half* KtL = KtH + DKT;

    const int hb = blockIdx.z;
    const int mBase = blockIdx.x * 128, lBase = blockIdx.y * 128;
    const int mblk = blockIdx.x;
    const int tid = threadIdx.x;
    const int wid = tid >> 5, lane = tid & 31;
    const int wl = wid & 3, wm = wid >> 2;     // 4 l-groups x 2 m-groups (32l x 64m)
    const int r = lane >> 2, c = lane & 3;
    const int lr = lane & 7, g = lane >> 3;

    const __half* gQrH = g_QrHi + ((size_t)hb*Ld + lBase)*Kd;
    const __half* gQrL = g_QrLo + ((size_t)hb*Ld + lBase)*Kd;
    const __half* gQtH = g_QtHi + ((size_t)hb*Ld + lBase)*Kd;
    const __half* gQtL = g_QtLo + ((size_t)hb*Ld + lBase)*Kd;
    const __half* gKrH = g_KrHi + ((size_t)hb*Md + mBase)*Kd;
    const __half* gKrL = g_KrLo + ((size_t)hb*Md + mBase)*Kd;
    const __half* gKtH = g_KtHi + ((size_t)hb*Md + mBase)*Kd;
    const __half* gKtL = g_KtLo + ((size_t)hb*Md + mBase)*Kd;

    // Group 1: R-stream operands (QrH, QrL, KrH, KrL)
    {
        const __half* gsrc[4] = {gQrH, gQrL, gKrH, gKrL};
        __half* sdst[4] = {QrH, QrL, KrH, KrL};
        #pragma unroll
        for (int s = 0; s < 4; s++) {
            uint32_t sb = smem_u32(sdst[s]);
            #pragma unroll
            for (int p = 0; p < 4; p++) {
                int id = tid + p * 256;
                int row = id >> 3, ch = id & 7;
                CP_ASYNC16(sb + (uint32_t)(row * DST + ch * 8) * 2,
                           gsrc[s] + (size_t)row * Kd + ch * 8);
            }
        }
        CP_COMMIT();
    }
    // Group 2: T-stream operands (QtH, QtL, KtH, KtL)
    {
        const __half* gsrc[4] = {gQtH, gQtL, gKtH, gKtL};
        __half* sdst[4] = {QtH, QtL, KtH, KtL};
        #pragma unroll
        for (int s = 0; s < 4; s++) {
            uint32_t sb = smem_u32(sdst[s]);
            #pragma unroll
            for (int p = 0; p < 4; p++) {
                int id = tid + p * 256;
                int row = id >> 3, ch = id & 7;
                CP_ASYNC16(sb + (uint32_t)(row * DST + ch * 8) * 2,
                           gsrc[s] + (size_t)row * Kd + ch * 8);
            }
        }
        CP_COMMIT();
    }

    uint32_t aoff[2];
    #pragma unroll
    for (int af = 0; af < 2; af++)
        aoff[af] = (uint32_t)((wl*32 + af*16 + lr + ((g & 1) << 3)) * DST + ((g >> 1) << 3)) * 2;
    const uint32_t boff = (uint32_t)((wm*64 + lr + ((g >> 1) << 3)) * DST + ((g & 1) << 3)) * 2;

    float accR[2][8][4] = {}, accT[2][8][4] = {};   // [af][nt][reg]

    // ---- stream R (group 1 loads done; group 2 still in flight) ----
    CP_WAIT1();
    __syncthreads();
    {
        const uint32_t uQH = smem_u32(QrH), uQL = smem_u32(QrL);
        const uint32_t uKH = smem_u32(KrH), uKL = smem_u32(KrL);
        #pragma unroll
        for (int ks = 0; ks < 4; ks++) {
            const uint32_t ko = ks * 32;
            uint32_t qh[2][4], ql[2][4];
            ldsm_x4(qh[0], uQH + aoff[0] + ko);
            ldsm_x4(qh[1], uQH + aoff[1] + ko);
            ldsm_x4(ql[0], uQL + aoff[0] + ko);
            ldsm_x4(ql[1], uQL + aoff[1] + ko);
            #pragma unroll
            for (int np = 0; np < 4; np++) {
                const uint32_t no = (uint32_t)(np * 16 * DST) * 2;
                uint32_t kh[4], kl[4];
                ldsm_x4(kh, uKH + boff + no + ko);
                ldsm_x4(kl, uKL + boff + no + ko);
                #pragma unroll
                for (int af = 0; af < 2; af++)
                    #pragma unroll
                    for (int hn = 0; hn < 2; hn++) {
                        int nt = np * 2 + hn;
                        uint32_t b0 = hn * 2, b1 = hn * 2 + 1;
                        mma_f16(accR[af][nt], qh[af][0], qh[af][1], qh[af][2], qh[af][3], kh[b0], kh[b1]);
                        mma_f16(accR[af][nt], qh[af][0], qh[af][1], qh[af][2], qh[af][3], kl[b0], kl[b1]);
                        mma_f16(accR[af][nt], ql[af][0], ql[af][1], ql[af][2], ql[af][3], kh[b0], kh[b1]);
                    }
            }
        }
    }
    // ---- stream T ----
    CP_WAIT0();
    __syncthreads();
    {
        const uint32_t uQH = smem_u32(QtH), uQL = smem_u32(QtL);
        const uint32_t uKH = smem_u32(KtH), uKL = smem_u32(KtL);
        #pragma unroll
        for (int ks = 0; ks < 4; ks++) {
            const uint32_t ko = ks * 32;
            uint32_t qh[2][4], ql[2][4];
            ldsm_x4(qh[0], uQH + aoff[0] + ko);
            ldsm_x4(qh[1], uQH + aoff[1] + ko);
            ldsm_x4(ql[0], uQL + aoff[0] + ko);
            ldsm_x4(ql[1], uQL + aoff[1] + ko);
            #pragma unroll
            for (int np = 0; np < 4; np++) {
                const uint32_t no = (uint32_t)(np * 16 * DST) * 2;
                uint32_t kh[4], kl[4];
                ldsm_x4(kh, uKH + boff + no + ko);
                ldsm_x4(kl, uKL + boff + no + ko);
                #pragma unroll
                for (int af = 0; af < 2; af++)
                    #pragma unroll
                    for (int hn = 0; hn < 2; hn++) {
                        int nt = np * 2 + hn;
                        uint32_t b0 = hn * 2, b1 = hn * 2 + 1;
                        mma_f16(accT[af][nt], qh[af][0], qh[af][1], qh[af][2], qh[af][3], kh[b0], kh[b1]);
                        mma_f16(accT[af][nt], qh[af][0], qh[af][1], qh[af][2], qh[af][3], kl[b0], kl[b1]);
                        mma_f16(accT[af][nt], ql[af][0], ql[af][1], ql[af][2], ql[af][3], kh[b0], kh[b1]);
                    }
            }
        }
    }

    // ---- epilogue: direct scattered STG + partial maxes ----
    float pm[3][2][2];   // [stream][af][half]
    #pragma unroll
    for (int s = 0; s < 3; s++)
        #pragma unroll
        for (int af = 0; af < 2; af++) { pm[s][af][0] = -1e30f; pm[s][af][1] = -1e30f; }

    #pragma unroll
    for (int af = 0; af < 2; af++) {
        const int lrow0 = lBase + wl*32 + af*16 + r;
        float* sR0 = g_Srgb + ((size_t)hb * Ld + lrow0) * Md + mBase + wm*64;
        float* sR1 = sR0 + 8 * Md;
        float* sT0 = g_St   + ((size_t)hb * Ld + lrow0) * Md + mBase + wm*64;
        float* sT1 = sT0 + 8 * Md;
        #pragma unroll
        for (int nt = 0; nt < 8; nt++) {
            int col = nt * 8 + 2 * c;
            *reinterpret_cast<float2*>(sR0 + col) = make_float2(accR[af][nt][0], accR[af][nt][1]);
            *reinterpret_cast<float2*>(sR1 + col) = make_float2(accR[af][nt][2], accR[af][nt][3]);
            *reinterpret_cast<float2*>(sT0 + col) = make_float2(accT[af][nt][0], accT[af][nt][1]);
            *reinterpret_cast<float2*>(sT1 + col) = make_float2(accT[af][nt][2], accT[af][nt][3]);
            pm[0][af][0] = fmaxf(pm[0][af][0], fmaxf(accR[af][nt][0], accR[af][nt][1]));
            pm[0][af][1] = fmaxf(pm[0][af][1], fmaxf(accR[af][nt][2], accR[af][nt][3]));
            pm[1][af][0] = fmaxf(pm[1][af][0], fmaxf(accT[af][nt][0], accT[af][nt][1]));
            pm[1][af][1] = fmaxf(pm[1][af][1], fmaxf(accT[af][nt][2], accT[af][nt][3]));
            pm[2][af][0] = fmaxf(pm[2][af][0], fmaxf(accR[af][nt][0]*accT[af][nt][0],
                                                     accR[af][nt][1]*accT[af][nt][1]));
            pm[2][af][1] = fmaxf(pm[2][af][1], fmaxf(accR[af][nt][2]*accT[af][nt][2],
                                                     accR[af][nt][3]*accT[af][nt][3]));
        }
    }
    #pragma unroll
    for (int s = 0; s < 3; s++)
        #pragma unroll
        for (int af = 0; af < 2; af++)
            #pragma unroll
            for (int hf = 0; hf < 2; hf++) {
                pm[s][af][hf] = fmaxf(pm[s][af][hf], __shfl_xor_sync(0xffffffffu, pm[s][af][hf], 1));
                pm[s][af][hf] = fmaxf(pm[s][af][hf], __shfl_xor_sync(0xffffffffu, pm[s][af][hf], 2));
            }
    if (c == 0) {
        #pragma unroll
        for (int af = 0; af < 2; af++)
            #pragma unroll
            for (int hf = 0; hf < 2; hf++) {
                size_t row = (size_t)hb * Ld + lBase + wl*32 + af*16 + r + hf*8;
                int slot = mblk * 2 + wm;       // 16 mblks x 2 wm = 32 slots
                g_pmax[row*96 +      slot] = pm[0][af][hf];
                g_pmax[row*96 + 32 + slot] = pm[1][af][hf];
                g_pmax[row*96 + 64 + slot] = pm[2][af][hf];
            }
    }
}

// =====================================================================
// Kernel 3: stats — reduce 32 partial-max slots, one pass ex2.f16x2.
// =====================================================================
__global__ __launch_bounds__(256)
void stats_kernel()
{
    const int row = blockIdx.x;
    const float* sr = g_Srgb + (size_t)row * Md;
    const float* st = g_St   + (size_t)row * Md;
    __half* pr = g_PrH + (size_t)row * Md;
    __half* pt = g_PtH + (size_t)row * Md;
    __half* px = g_PxH + (size_t)row * Md;
    const int tid = threadIdx.x;
    const int lane = tid & 31, wid = tid >> 5;
    __shared__ float smax[3];
    __shared__ float sm[8][3];

    if (wid < 3) {
        float v = g_pmax[(size_t)row * 96 + wid*32 + lane];
        #pragma unroll
        for (int o = 16; o > 0; o >>= 1)
            v = fmaxf(v, __shfl_xor_sync(0xffffffffu, v, o));
        if (lane == 0) smax[wid] = v;
    }
    __syncthreads();

    const float L2E = 1.44269504088896340736f;
    const float m1 = 100.f * smax[0], m2 = 100.f * smax[1], m3 = smax[2];
    const float c100 = 100.f * L2E;
    const float mm1 = m1 * L2E, mm2 = m2 * L2E, mm3 = m3 * L2E;

    float s1 = 0.f, s2 = 0.f, s3 = 0.f;
    #pragma unroll
    for (int it = 0; it < 2; it++) {
        int i = (tid + it * 256) * 4;
        float4 a = *reinterpret_cast<const float4*>(sr + i);
        float4 b = *reinterpret_cast<const float4*>(st + i);

        uint32_t u0 = h2exp2u(pack_h2(fmaf(c100, a.x, -mm1), fmaf(c100, a.y, -mm1)));
        uint32_t u1 = h2exp2u(pack_h2(fmaf(c100, a.z, -mm1), fmaf(c100, a.w, -mm1)));
        *reinterpret_cast<uint2*>(pr + i) = make_uint2(u0, u1);
        float2 f0 = h2f2(u0), f1 = h2f2(u1);
        s1 += (f0.x + f0.y) + (f1.x + f1.y);

        u0 = h2exp2u(pack_h2(fmaf(c100, b.x, -mm2), fmaf(c100, b.y, -mm2)));
        u1 = h2exp2u(pack_h2(fmaf(c100, b.z, -mm2), fmaf(c100, b.w, -mm2)));
        *reinterpret_cast<uint2*>(pt + i) = make_uint2(u0, u1);
        f0 = h2f2(u0); f1 = h2f2(u1);
        s2 += (f0.x + f0.y) + (f1.x + f1.y);

        u0 = h2exp2u(pack_h2(fmaf(L2E, a.x*b.x, -mm3), fmaf(L2E, a.y*b.y, -mm3)));
        u1 = h2exp2u(pack_h2(fmaf(L2E, a.z*b.z, -mm3), fmaf(L2E, a.w*b.w, -mm3)));
        *reinterpret_cast<uint2*>(px + i) = make_uint2(u0, u1);
        f0 = h2f2(u0); f1 = h2f2(u1);
        s3 += (f0.x + f0.y) + (f1.x + f1.y);
    }
    #pragma unroll
    for (int o = 16; o > 0; o >>= 1) {
        s1 += __shfl_xor_sync(0xffffffffu, s1, o);
        s2 += __shfl_xor_sync(0xffffffffu, s2, o);
        s3 += __shfl_xor_sync(0xffffffffu, s3, o);
    }
    if (lane == 0) { sm[wid][0] = s1; sm[wid][1] = s2; sm[wid][2] = s3; }
    __syncthreads();
    if (tid == 0) {
        s1 = s2 = s3 = 0.f;
        #pragma unroll
        for (int w = 0; w < 8; w++) { s1 += sm[w][0]; s2 += sm[w][1]; s3 += sm[w][2]; }
        float* o = g_stats + (size_t)row * 6;
        o[0] = m1; o[1] = s1; o[2] = m2; o[3] = s2; o[4] = m3; o[5] = s3;
    }
}

// =====================================================================
// Kernel 4: attend — fp16 mma, tile 64l x 128f, 2-stage cp.async double
// buffer. 8 warps = 2(l) x 4(f), each 32x32. (unchanged from R11)
// grid: (F/128, L/64, HB), block 256, dynamic smem 71680 B
// =====================================================================
#define AST    40
#define PTILE  (64*AST)             // 2560 halves per P tile
#define VTILE  (128*AST)            // 5120 halves per V tile
#define ASTG   (3*PTILE + 2*VTILE)  // 17920 halves per stage
#define ATT_SMEM (2*ASTG*2)         // 71680 bytes
#define NCHUNK (Md/32)              // 64

__global__ __launch_bounds__(256, 1)
void attend_mma_kernel(float* __restrict__ out)
{
    extern __shared__ __half ash[];
    const int hb = blockIdx.z;
    const int h  = hb / Bd, b = hb % Bd;
    const int fBase = blockIdx.x * 128, lBase = blockIdx.y * 64;
    const int tid = threadIdx.x;
    const int wid = tid >> 5, lane = tid & 31;
    const int wl = wid & 1, wf = wid >> 1;     // 2 l-groups x 4 f-groups
    const int r = lane >> 2, c = lane & 3;
    const int lr = lane & 7, g = lane >> 3;

    const __half* s0 = g_PrH + ((size_t)hb * Ld + lBase) * Md;
    const __half* s1 = g_PtH + ((size_t)hb * Ld + lBase) * Md;
    const __half* s2 = g_PxH + ((size_t)hb * Ld + lBase) * Md;
    const __half* s3 = g_VrT + ((size_t)(b * Fd + fBase)) * Md;
    const __half* s4 = g_VtT + ((size_t)(b * Fd + fBase)) * Md;

    const uint32_t sbase = smem_u32(ash);
    const int prow = tid >> 2, pseg = tid & 3;               // 64 rows x 4 16B-segs
    const uint32_t dP  = (uint32_t)(prow * AST + pseg * 8) * 2;
    const uint32_t dV0 = dP;                                  // V row prow
    const uint32_t dV1 = (uint32_t)((prow + 64) * AST + pseg * 8) * 2;
    const size_t gP  = (size_t)prow * Md + pseg * 8;
    const size_t gV1 = (size_t)(prow + 64) * Md + pseg * 8;

    // ldmatrix fragment offsets within a stage (bytes)
    uint32_t aoff[2];
    #pragma unroll
    for (int af = 0; af < 2; af++)
        aoff[af] = (uint32_t)((wl*32 + af*16 + lr + ((g & 1) << 3)) * AST + ((g >> 1) << 3)) * 2;
    const uint32_t boff = (uint32_t)((wf*32 + lr + ((g >> 1) << 3)) * AST + ((g & 1) << 3)) * 2;

    float acc[4][2][4][4] = {};   // [out][afrag][ntile][reg]

    // prologue: stage 0 <- chunk 0
    {
        uint32_t st = sbase;
        CP_ASYNC16(st + 0*PTILE*2 + dP, s0 + gP);
        CP_ASYNC16(st + 1*PTILE*2 + dP, s1 + gP);
        CP_ASYNC16(st + 2*PTILE*2 + dP, s2 + gP);
        CP_ASYNC16(st + 3*PTILE*2 + dV0, s3 + gP);
        CP_ASYNC16(st + 3*PTILE*2 + dV1, s3 + gV1);
        CP_ASYNC16(st + (3*PTILE + VTILE)*2 + dV0, s4 + gP);
        CP_ASYNC16(st + (3*PTILE + VTILE)*2 + dV1, s4 + gV1);
    }
    CP_COMMIT();

    for (int cc = 0; cc < NCHUNK; cc++) {
        if (cc + 1 < NCHUNK) {
            size_t o1 = (size_t)(cc + 1) * 32;
            uint32_t st = sbase + (uint32_t)(((cc + 1) & 1) * ASTG) * 2;
            CP_ASYNC16(st + 0*PTILE*2 + dP, s0 + gP + o1);
            CP_ASYNC16(st + 1*PTILE*2 + dP, s1 + gP + o1);
            CP_ASYNC16(st + 2*PTILE*2 + dP, s2 + gP + o1);
            CP_ASYNC16(st + 3*PTILE*2 + dV0, s3 + gP + o1);
            CP_ASYNC16(st + 3*PTILE*2 + dV1, s3 + gV1 + o1);
            CP_ASYNC16(st + (3*PTILE + VTILE)*2 + dV0, s4 + gP + o1);
            CP_ASYNC16(st + (3*PTILE + VTILE)*2 + dV1, s4 + gV1 + o1);
        }
        CP_COMMIT();
        CP_WAIT1();
        __syncthreads();

        const uint32_t stg = sbase + (uint32_t)((cc & 1) * ASTG) * 2;
        const uint32_t uPr = stg;
        const uint32_t uPt = stg + 1*PTILE*2;
        const uint32_t uPx = stg + 2*PTILE*2;
        const uint32_t uVr = stg + 3*PTILE*2;
        const uint32_t uVt = stg + (3*PTILE + VTILE)*2;

        #pragma unroll
        for (int ks = 0; ks < 2; ks++) {
            const uint32_t ko = ks * 32;
            uint32_t ar[2][4], at[2][4], ax[2][4];
            #pragma unroll
            for (int af = 0; af < 2; af++) {
                ldsm_x4(ar[af], uPr + aoff[af] + ko);
                ldsm_x4(at[af], uPt + aoff[af] + ko);
                ldsm_x4(ax[af], uPx + aoff[af] + ko);
            }
            #pragma unroll
            for (int np = 0; np < 2; np++) {
                const uint32_t no = (uint32_t)(np * 16 * AST) * 2;
                uint32_t vr[4], vt[4];
                ldsm_x4(vr, uVr + boff + no + ko);
                ldsm_x4(vt, uVt + boff + no + ko);
                #pragma unroll
                for (int af = 0; af < 2; af++) {
                    #pragma unroll
                    for (int hn = 0; hn < 2; hn++) {
                        int nt = np * 2 + hn;
                        uint32_t b0 = hn * 2, b1 = hn * 2 + 1;
                        mma_f16(acc[0][af][nt], ar[af][0], ar[af][1], ar[af][2], ar[af][3], vr[b0], vr[b1]);
                        mma_f16(acc[1][af][nt], at[af][0], at[af][1], at[af][2], at[af][3], vt[b0], vt[b1]);
                        mma_f16(acc[2][af][nt], ax[af][0], ax[af][1], ax[af][2], ax[af][3], vt[b0], vt[b1]);
                        mma_f16(acc[3][af][nt], ax[af][0], ax[af][1], ax[af][2], ax[af][3], vr[b0], vr[b1]);
                    }
                }
            }
        }
        __syncthreads();
    }

    const size_t OSZ = (size_t)Ld * Bd * HFd;
    #pragma unroll
    for (int af = 0; af < 2; af++) {
        const int l0 = lBase + wl * 32 + af * 16 + r;
        const int l1 = l0 + 8;
        const float* st0 = g_stats + ((size_t)hb * Ld + l0) * 6;
        const float* st1 = g_stats + ((size_t)hb * Ld + l1) * 6;
        const float inv0[4] = {1.f/st0[1], 1.f/st0[3], 1.f/st0[5], 1.f/st0[5]};
        const float inv1[4] = {1.f/st1[1], 1.f/st1[3], 1.f/st1[5], 1.f/st1[5]};
        const size_t base0 = ((size_t)l0 * Bd + b) * HFd + (size_t)h * Fd;
        const size_t base1 = ((size_t)l1 * Bd + b) * HFd + (size_t)h * Fd;
        #pragma unroll
        for (int d = 0; d < 4; d++) {
            #pragma unroll
            for (int nt = 0; nt < 4; nt++) {
                int f = fBase + wf * 32 + nt * 8 + 2 * c;
                *reinterpret_cast<float2*>(out + d*OSZ + base0 + f) =
                    make_float2(acc[d][af][nt][0] * inv0[d], acc[d][af][nt][1] * inv0[d]);
                *reinterpret_cast<float2*>(out + d*OSZ + base1 + f) =
                    make_float2(acc[d][af][nt][2] * inv1[d], acc[d][af][nt][3] * inv1[d]);
            }
        }
    }
}

// =====================================================================
extern "C" void kernel_launch(void* const* d_in, const int* in_sizes, int n_in,
                              void* d_out, int out_size)
{
    const float* rgbquery  = (const float*)d_in[0];
    const float* rgbkey    = (const float*)d_in[1];
    const float* rgbvalue  = (const float*)d_in[2];
    const float* tquery    = (const float*)d_in[3];
    const float* tkey      = (const float*)d_in[4];
    const float* tvalue    = (const float*)d_in[5];
    const float* fusekey   = (const float*)d_in[6];
    const float* fusevalue = (const float*)d_in[7];
    const float* WK_w      = (const float*)d_in[8];
    const float* WK_b      = (const float*)d_in[9];
    float* out = (float*)d_out;

    cudaFuncSetAttribute(proj_mma_kernel, cudaFuncAttributeMaxDynamicSharedMemorySize, PROJ_SMEM);
    cudaFuncSetAttribute(dot_kernel, cudaFuncAttributeMaxDynamicSharedMemorySize, DOT_SMEM);
    cudaFuncSetAttribute(attend_mma_kernel, cudaFuncAttributeMaxDynamicSharedMemorySize, ATT_SMEM);

    split_kernel<<<dim3(1024, 6), 256>>>(rgbquery, tquery, rgbkey, tkey, fusekey, WK_w);
    vtrans_kernel<<<dim3(Md/64, Fd/64, Bd*2), 256>>>(rgbvalue, tvalue, fusevalue);
    proj_mma_kernel<<<dim3(192, Hd), 256, PROJ_SMEM>>>(WK_b);
    dot_kernel<<<dim3(Md/128, Ld/128, HBd), 256, DOT_SMEM>>>();
    stats_kernel<<<HBd*Ld, 256>>>();
    attend_mma_kernel<<<dim3(Fd/128, Ld/64, HBd), 256, ATT_SMEM>>>(out);
}